// round 7
// baseline (speedup 1.0000x reference)
#include <cuda_runtime.h>
#include <cuda_bf16.h>
#include <math.h>
#include <stdint.h>

// ---------------------------------------------------------------------------
// Scratch (__device__ globals; no allocations allowed)
// ---------------------------------------------------------------------------
__device__ float g_Q [(size_t)4096 * 1024];   // out-proj result (a+x)
__device__ float g_K [(size_t)4096 * 1024];   // h = LN1(...)
__device__ float g_V [(size_t)4096 * 1024];   // ffn2 result fp32
__device__ float g_Y [(size_t)4096 * 1024];   // Yhi/Ylo bf16 halves
__device__ unsigned short g_Ahi[(size_t)4096 * 4096];
__device__ unsigned short g_Alo[(size_t)4096 * 4096];
__device__ unsigned short g_Whi[(size_t)12 * 1024 * 1024];
__device__ unsigned short g_Wlo[(size_t)12 * 1024 * 1024];
__device__ unsigned short g_Qhi [(size_t)4096 * 1024];
__device__ unsigned short g_Qlo [(size_t)4096 * 1024];
__device__ unsigned short g_Khi [(size_t)4096 * 1024];
__device__ unsigned short g_Klo [(size_t)4096 * 1024];
__device__ unsigned short g_Vhi [(size_t)4096 * 1024];  // V natural layout
__device__ unsigned short g_Vlo [(size_t)4096 * 1024];

__device__ __forceinline__ uint32_t smem_u32(const void* p) {
    uint32_t a;
    asm("{ .reg .u64 t; cvta.to.shared.u64 t, %1; cvt.u32.u64 %0, t; }"
        : "=r"(a) : "l"(p));
    return a;
}
__device__ __forceinline__ void cpa16(uint32_t s, const void* g) {
    asm volatile("cp.async.cg.shared.global [%0], [%1], 16;"
                 :: "r"(s), "l"(__cvta_generic_to_global(g)) : "memory");
}
__device__ __forceinline__ void cp_commit() {
    asm volatile("cp.async.commit_group;" ::: "memory");
}
template<int N>
__device__ __forceinline__ void cp_wait() {
    asm volatile("cp.async.wait_group %0;" :: "n"(N) : "memory");
}
__device__ __forceinline__ void ldm_x4(uint32_t* r, uint32_t saddr) {
    asm volatile("ldmatrix.sync.aligned.m8n8.x4.shared.b16 {%0,%1,%2,%3}, [%4];"
                 : "=r"(r[0]), "=r"(r[1]), "=r"(r[2]), "=r"(r[3]) : "r"(saddr));
}
__device__ __forceinline__ void ldm_x4_t(uint32_t* r, uint32_t saddr) {
    asm volatile("ldmatrix.sync.aligned.m8n8.x4.trans.shared.b16 {%0,%1,%2,%3}, [%4];"
                 : "=r"(r[0]), "=r"(r[1]), "=r"(r[2]), "=r"(r[3]) : "r"(saddr));
}
__device__ __forceinline__ void mma16816(float* c, const uint32_t* a, const uint32_t* b) {
    asm volatile("mma.sync.aligned.m16n8k16.row.col.f32.bf16.bf16.f32 "
                 "{%0,%1,%2,%3}, {%4,%5,%6,%7}, {%8,%9}, {%0,%1,%2,%3};"
                 : "+f"(c[0]), "+f"(c[1]), "+f"(c[2]), "+f"(c[3])
                 : "r"(a[0]), "r"(a[1]), "r"(a[2]), "r"(a[3]),
                   "r"(b[0]), "r"(b[1]));
}
__device__ __forceinline__ float gelu_f(float v) {
    return 0.5f * v * (1.0f + erff(v * 0.70710678118654752f));
}
__device__ __forceinline__ void bfsplit2(float x, float y, uint32_t& hi, uint32_t& lo) {
    __nv_bfloat16 hx = __float2bfloat16(x), hy = __float2bfloat16(y);
    hi = ((uint32_t)(*(unsigned short*)&hy) << 16) | (uint32_t)(*(unsigned short*)&hx);
    __nv_bfloat16 lx = __float2bfloat16(x - __bfloat162float(hx));
    __nv_bfloat16 ly = __float2bfloat16(y - __bfloat162float(hy));
    lo = ((uint32_t)(*(unsigned short*)&ly) << 16) | (uint32_t)(*(unsigned short*)&lx);
}

// ---------------------------------------------------------------------------
// Tensor-core dense GEMM. K-chunk 64, 3-stage pipeline, ROWB 144.
// C = (Ahi+Alo)[M,K] @ (Whi+Wlo)[N,K]^T (+bias | +bias,gelu | +bias+residual)
// Outputs per z: optional fp32 Cf, optional bf16 hi/lo (Ch/Cl).
// ---------------------------------------------------------------------------
#define ROWB   144
#define TILEB  (128 * ROWB)          // 18432
#define STAGEB (4 * TILEB)           // 73728
#define NSTAGE 3
#define TG_SMEM (NSTAGE * STAGEB)    // 221184

template<int EPI>
__global__ __launch_bounds__(256, 1)
void tgemm_kernel(const unsigned short* __restrict__ Ahi16,
                  const unsigned short* __restrict__ Alo16,
                  const unsigned short* __restrict__ Whi16,
                  const unsigned short* __restrict__ Wlo16,
                  size_t wz,
                  const float* __restrict__ bias0, const float* __restrict__ bias1,
                  const float* __restrict__ bias2,
                  const float* __restrict__ R,
                  float* __restrict__ Cf0, float* __restrict__ Cf1, float* __restrict__ Cf2,
                  unsigned short* __restrict__ Ch0, unsigned short* __restrict__ Ch1,
                  unsigned short* __restrict__ Ch2,
                  unsigned short* __restrict__ Cl0, unsigned short* __restrict__ Cl1,
                  unsigned short* __restrict__ Cl2,
                  int M, int N, int K)
{
    extern __shared__ __align__(128) char smem[];
    const int z = blockIdx.z;
    const unsigned short* Bh = Whi16 + wz * z;
    const unsigned short* Bl = Wlo16 + wz * z;
    const float* bias = (z == 0) ? bias0 : (z == 1) ? bias1 : bias2;
    float*          Cf = (z == 0) ? Cf0 : (z == 1) ? Cf1 : Cf2;
    unsigned short* Ch = (z == 0) ? Ch0 : (z == 1) ? Ch1 : Ch2;
    unsigned short* Cl = (z == 0) ? Cl0 : (z == 1) ? Cl1 : Cl2;

    const uint32_t sbase = smem_u32(smem);
    const int t    = threadIdx.x;
    const int wid  = t >> 5;
    const int lane = t & 31;
    const int m0   = blockIdx.y * 128;
    const int n0   = blockIdx.x * 128;
    const int wm   = (wid & 1) * 64;
    const int wn   = (wid >> 1) * 32;

    // loader: row = t>>1 (0..127), half = t&1 (64B each); 4 cpa16 per tile
    const int lrow = t >> 1;
    const int half = t & 1;
    const unsigned short* pAh = Ahi16 + (size_t)(m0 + lrow) * K + half * 32;
    const unsigned short* pAl = Alo16 + (size_t)(m0 + lrow) * K + half * 32;
    const unsigned short* pBh = Bh    + (size_t)(n0 + lrow) * K + half * 32;
    const unsigned short* pBl = Bl    + (size_t)(n0 + lrow) * K + half * 32;
    const uint32_t sRow = (uint32_t)lrow * ROWB + half * 64;

    #define LOAD_STAGE(cc, ss) do {                                         \
        const uint32_t sb_ = sbase + (ss) * STAGEB + sRow;                   \
        const size_t  ko_ = (size_t)(cc) * 64;                               \
        _Pragma("unroll")                                                    \
        for (int i_ = 0; i_ < 4; ++i_) {                                     \
            cpa16(sb_ + 0 * TILEB + i_ * 16, pAh + ko_ + i_ * 8);            \
            cpa16(sb_ + 1 * TILEB + i_ * 16, pAl + ko_ + i_ * 8);            \
            cpa16(sb_ + 2 * TILEB + i_ * 16, pBh + ko_ + i_ * 8);            \
            cpa16(sb_ + 3 * TILEB + i_ * 16, pBl + ko_ + i_ * 8);            \
        }                                                                    \
    } while (0)

    const uint32_t laneA = (uint32_t)(lane & 15) * ROWB + (lane >> 4) * 16;
    const uint32_t laneB = (uint32_t)((lane & 7) + ((lane >> 4) << 3)) * ROWB
                         + ((lane >> 3) & 1) * 16;

    float acc[4][4][4];
    #pragma unroll
    for (int i = 0; i < 4; ++i)
        #pragma unroll
        for (int j = 0; j < 4; ++j)
            #pragma unroll
            for (int q = 0; q < 4; ++q) acc[i][j][q] = 0.0f;

    const int NC = K >> 6;   // chunks of 64
    LOAD_STAGE(0, 0); cp_commit();
    LOAD_STAGE(1, 1); cp_commit();

    for (int c = 0; c < NC; ++c) {
        const int s = c % NSTAGE;
        cp_wait<1>();
        __syncthreads();
        if (c + 2 < NC) LOAD_STAGE(c + 2, (c + 2) % NSTAGE);
        cp_commit();

        const uint32_t stg = sbase + s * STAGEB;
        #pragma unroll
        for (int ks = 0; ks < 4; ++ks) {
            const uint32_t kb = ks * 32;
            uint32_t ah[4][4], al[4][4], bh[4][2], bl[4][2];
            #pragma unroll
            for (int mf = 0; mf < 4; ++mf) {
                const uint32_t ra = stg + (uint32_t)(wm + mf * 16) * ROWB + laneA + kb;
                ldm_x4(ah[mf], ra + 0 * TILEB);
                ldm_x4(al[mf], ra + 1 * TILEB);
            }
            #pragma unroll
            for (int p = 0; p < 2; ++p) {
                uint32_t rb[4], rl[4];
                const uint32_t ra = stg + (uint32_t)(wn + p * 16) * ROWB + laneB + kb;
                ldm_x4(rb, ra + 2 * TILEB);
                ldm_x4(rl, ra + 3 * TILEB);
                bh[p * 2 + 0][0] = rb[0]; bh[p * 2 + 0][1] = rb[1];
                bh[p * 2 + 1][0] = rb[2]; bh[p * 2 + 1][1] = rb[3];
                bl[p * 2 + 0][0] = rl[0]; bl[p * 2 + 0][1] = rl[1];
                bl[p * 2 + 1][0] = rl[2]; bl[p * 2 + 1][1] = rl[3];
            }
            #pragma unroll
            for (int mf = 0; mf < 4; ++mf)
                #pragma unroll
                for (int nf = 0; nf < 4; ++nf) {
                    mma16816(acc[mf][nf], ah[mf], bh[nf]);
                    mma16816(acc[mf][nf], ah[mf], bl[nf]);
                    mma16816(acc[mf][nf], al[mf], bh[nf]);
                }
        }
    }

    const int rbase = lane >> 2;
    const int cbase = (lane & 3) * 2;
    #pragma unroll
    for (int mf = 0; mf < 4; ++mf) {
        #pragma unroll
        for (int nf = 0; nf < 4; ++nf) {
            const int col = n0 + wn + nf * 8 + cbase;
            const float2 bb = *(const float2*)&bias[col];
            #pragma unroll
            for (int h = 0; h < 2; ++h) {
                const int row = m0 + wm + mf * 16 + rbase + h * 8;
                float2 rv;
                rv.x = acc[mf][nf][h * 2 + 0] + bb.x;
                rv.y = acc[mf][nf][h * 2 + 1] + bb.y;
                if (EPI == 1) { rv.x = gelu_f(rv.x); rv.y = gelu_f(rv.y); }
                if (EPI == 2) {
                    const float2 rr = *(const float2*)&R[(size_t)row * N + col];
                    rv.x += rr.x; rv.y += rr.y;
                }
                if (Cf) *(float2*)&Cf[(size_t)row * N + col] = rv;
                if (Ch) {
                    uint32_t hi, lo;
                    bfsplit2(rv.x, rv.y, hi, lo);
                    *(uint32_t*)&Ch[(size_t)row * N + col] = hi;
                    *(uint32_t*)&Cl[(size_t)row * N + col] = lo;
                }
            }
        }
    }
    #undef LOAD_STAGE
}

// ---------------------------------------------------------------------------
// fp32 -> bf16 hi/lo split kernels
// ---------------------------------------------------------------------------
__device__ __forceinline__ void split1(float v, unsigned short& h, unsigned short& l) {
    __nv_bfloat16 hb = __float2bfloat16(v);
    __nv_bfloat16 lb = __float2bfloat16(v - __bfloat162float(hb));
    h = *(unsigned short*)&hb;
    l = *(unsigned short*)&lb;
}

__global__ __launch_bounds__(256)
void split_kernel(const float* __restrict__ X, unsigned short* __restrict__ hi,
                  unsigned short* __restrict__ lo, int n4)
{
    int i = blockIdx.x * 256 + threadIdx.x;
    if (i >= n4) return;
    float4 v = ((const float4*)X)[i];
    ushort4 h, l;
    split1(v.x, h.x, l.x); split1(v.y, h.y, l.y);
    split1(v.z, h.z, l.z); split1(v.w, h.w, l.w);
    ((ushort4*)hi)[i] = h;
    ((ushort4*)lo)[i] = l;
}

// transpose+split; z-fused for up to 4 equal-shaped weights
__global__ __launch_bounds__(256)
void tsplit_kernel(const float* __restrict__ W0, const float* __restrict__ W1,
                   const float* __restrict__ W2, const float* __restrict__ W3,
                   unsigned short* __restrict__ Thi, unsigned short* __restrict__ Tlo,
                   size_t zstride, int K, int N)
{
    __shared__ float s[32][33];
    const int z = blockIdx.z;
    const float* W = (z == 0) ? W0 : (z == 1) ? W1 : (z == 2) ? W2 : W3;
    unsigned short* Th = Thi + zstride * z;
    unsigned short* Tl = Tlo + zstride * z;
    const int tx = threadIdx.x, ty = threadIdx.y;
    const int nb = blockIdx.x * 32, kb = blockIdx.y * 32;
    #pragma unroll
    for (int i = 0; i < 4; ++i)
        s[ty + i * 8][tx] = W[(size_t)(kb + ty + i * 8) * N + nb + tx];
    __syncthreads();
    #pragma unroll
    for (int i = 0; i < 4; ++i) {
        const float v = s[tx][ty + i * 8];
        unsigned short h, l;
        split1(v, h, l);
        const size_t o = (size_t)(nb + ty + i * 8) * K + kb + tx;
        Th[o] = h; Tl[o] = l;
    }
}

// ---------------------------------------------------------------------------
// Flash attention via mma.sync; V in NATURAL layout via ldmatrix.trans.
// 3-stage KV pipeline. Output written directly as bf16 hi/lo.
// ---------------------------------------------------------------------------
#define AROWB   144
#define ATT_QLO 18432
#define ATT_KV  36864
#define ATT_STG 36864
#define ATT_NST 3
#define ATT_MB  (ATT_KV + ATT_NST * ATT_STG)
#define ATT_SMEM (ATT_MB + 1024)

__global__ __launch_bounds__(256, 1)
void attn_mma_kernel(const unsigned short* __restrict__ Qhi,
                     const unsigned short* __restrict__ Qlo,
                     const unsigned short* __restrict__ Khi,
                     const unsigned short* __restrict__ Klo,
                     const unsigned short* __restrict__ Vhi,
                     const unsigned short* __restrict__ Vlo,
                     const int* __restrict__ mask,
                     unsigned short* __restrict__ Yhi,
                     unsigned short* __restrict__ Ylo)
{
    extern __shared__ __align__(128) char smem[];
    const uint32_t sb = smem_u32(smem);
    const int t    = threadIdx.x;
    const int lane = t & 31;
    const int w    = t >> 5;
    const int q0   = blockIdx.x * 128;
    const int bh   = blockIdx.y;
    const int tokb = (bh >> 4) * 2048;
    const int colb = (bh & 15) * 64;

    const uint32_t laneA = (uint32_t)(lane & 15) * AROWB + (lane >> 4) * 16;
    const uint32_t laneB = (uint32_t)((lane & 7) + ((lane >> 4) << 3)) * AROWB
                         + ((lane >> 3) & 1) * 16;
    // trans lane map: lanes 0-7 -> k-rows 0-7, 8-15 -> k-rows 8-15 (n unit 0);
    //                 16-23 -> k-rows 0-7, 24-31 -> k-rows 8-15 (n unit 1)
    const uint32_t laneBT = (uint32_t)((lane & 7) + ((lane >> 3) & 1) * 8) * AROWB
                          + (lane >> 4) * 16;

    {
        const int row = t >> 1;
        const size_t g = (size_t)(tokb + q0 + row) * 1024 + colb;
        const uint32_t sr = (uint32_t)row * AROWB;
        #pragma unroll
        for (int i = 0; i < 4; ++i) {
            const int ch = (t & 1) * 4 + i;
            cpa16(sb + sr + ch * 16,           Qhi + g + ch * 8);
            cpa16(sb + ATT_QLO + sr + ch * 16, Qlo + g + ch * 8);
        }
    }

    auto LOADKV = [&](int tile, int s) {
        const int kv0 = tile * 64;
        const int row = t >> 2;
        const int q2  = t & 3;
        const uint32_t st = sb + ATT_KV + s * ATT_STG;
        const size_t gk = (size_t)(tokb + kv0 + row) * 1024 + colb;
        const uint32_t sr = (uint32_t)row * AROWB;
        #pragma unroll
        for (int i = 0; i < 2; ++i) {
            const int ch = q2 * 2 + i;
            cpa16(st +         sr + ch * 16, Khi + gk + ch * 8);
            cpa16(st +  9216 + sr + ch * 16, Klo + gk + ch * 8);
            cpa16(st + 18432 + sr + ch * 16, Vhi + gk + ch * 8);
            cpa16(st + 27648 + sr + ch * 16, Vlo + gk + ch * 8);
        }
        if (t < 64) {
            float* mb = (float*)(smem + ATT_MB) + s * 64;
            mb[t] = (mask[tokb + kv0 + t] == 0) ? -1e30f : 0.0f;
        }
    };

    LOADKV(0, 0); cp_commit();
    LOADKV(1, 1); cp_commit();
    LOADKV(2, 2); cp_commit();

    cp_wait<2>();
    __syncthreads();

    uint32_t qh[4][4], ql[4][4];
    #pragma unroll
    for (int fk = 0; fk < 4; ++fk) {
        const uint32_t ra = sb + (uint32_t)(w * 16) * AROWB + laneA + fk * 32;
        ldm_x4(qh[fk], ra);
        ldm_x4(ql[fk], ra + ATT_QLO);
    }

    float of[8][4];
    #pragma unroll
    for (int i = 0; i < 8; ++i)
        #pragma unroll
        for (int j = 0; j < 4; ++j) of[i][j] = 0.0f;
    float mA = -1e30f, mB = -1e30f, lA = 0.0f, lB = 0.0f;
    const int c0 = (lane & 3) * 2;

    for (int tile = 0; tile < 32; ++tile) {
        const int s = tile % ATT_NST;
        if (tile > 0) { cp_wait<2>(); __syncthreads(); }
        const uint32_t kst = sb + ATT_KV + s * ATT_STG;
        const float* mb = (const float*)(smem + ATT_MB) + s * 64;

        float sf[8][4];
        #pragma unroll
        for (int i = 0; i < 8; ++i)
            #pragma unroll
            for (int j = 0; j < 4; ++j) sf[i][j] = 0.0f;

        #pragma unroll
        for (int fk = 0; fk < 4; ++fk) {
            uint32_t kh[8][2], kl[8][2];
            #pragma unroll
            for (int p = 0; p < 4; ++p) {
                uint32_t r0[4], r1[4];
                const uint32_t ra = kst + (uint32_t)(p * 16) * AROWB + laneB + fk * 32;
                ldm_x4(r0, ra);
                ldm_x4(r1, ra + 9216);
                kh[p * 2 + 0][0] = r0[0]; kh[p * 2 + 0][1] = r0[1];
                kh[p * 2 + 1][0] = r0[2]; kh[p * 2 + 1][1] = r0[3];
                kl[p * 2 + 0][0] = r1[0]; kl[p * 2 + 0][1] = r1[1];
                kl[p * 2 + 1][0] = r1[2]; kl[p * 2 + 1][1] = r1[3];
            }
            #pragma unroll
            for (int nf = 0; nf < 8; ++nf) {
                mma16816(sf[nf], qh[fk], kh[nf]);
                mma16816(sf[nf], qh[fk], kl[nf]);
                mma16816(sf[nf], ql[fk], kh[nf]);
            }
        }

        float pmA = -1e30f, pmB = -1e30f;
        #pragma unroll
        for (int nf = 0; nf < 8; ++nf) {
            const float m0 = mb[nf * 8 + c0];
            const float m1 = mb[nf * 8 + c0 + 1];
            sf[nf][0] = fmaf(sf[nf][0], 0.125f, m0);
            sf[nf][1] = fmaf(sf[nf][1], 0.125f, m1);
            sf[nf][2] = fmaf(sf[nf][2], 0.125f, m0);
            sf[nf][3] = fmaf(sf[nf][3], 0.125f, m1);
            pmA = fmaxf(pmA, fmaxf(sf[nf][0], sf[nf][1]));
            pmB = fmaxf(pmB, fmaxf(sf[nf][2], sf[nf][3]));
        }
        pmA = fmaxf(pmA, __shfl_xor_sync(0xffffffffu, pmA, 1));
        pmA = fmaxf(pmA, __shfl_xor_sync(0xffffffffu, pmA, 2));
        pmB = fmaxf(pmB, __shfl_xor_sync(0xffffffffu, pmB, 1));
        pmB = fmaxf(pmB, __shfl_xor_sync(0xffffffffu, pmB, 2));
        const float mnA = fmaxf(mA, pmA), mnB = fmaxf(mB, pmB);
        const float alA = __expf(mA - mnA), alB = __expf(mB - mnB);
        mA = mnA; mB = mnB;
        float rsA = 0.0f, rsB = 0.0f;
        #pragma unroll
        for (int nf = 0; nf < 8; ++nf) {
            sf[nf][0] = __expf(sf[nf][0] - mnA);
            sf[nf][1] = __expf(sf[nf][1] - mnA);
            sf[nf][2] = __expf(sf[nf][2] - mnB);
            sf[nf][3] = __expf(sf[nf][3] - mnB);
            rsA += sf[nf][0] + sf[nf][1];
            rsB += sf[nf][2] + sf[nf][3];
        }
        rsA += __shfl_xor_sync(0xffffffffu, rsA, 1);
        rsA += __shfl_xor_sync(0xffffffffu, rsA, 2);
        rsB += __shfl_xor_sync(0xffffffffu, rsB, 1);
        rsB += __shfl_xor_sync(0xffffffffu, rsB, 2);
        lA = lA * alA + rsA;
        lB = lB * alB + rsB;
        #pragma unroll
        for (int nf = 0; nf < 8; ++nf) {
            of[nf][0] *= alA; of[nf][1] *= alA;
            of[nf][2] *= alB; of[nf][3] *= alB;
        }

        // O += (Phi+Plo) @ V, V natural layout via ldmatrix.trans
        #pragma unroll
        for (int fk = 0; fk < 4; ++fk) {
            uint32_t aHi[4], aLo[4];
            bfsplit2(sf[2 * fk][0],     sf[2 * fk][1],     aHi[0], aLo[0]);
            bfsplit2(sf[2 * fk][2],     sf[2 * fk][3],     aHi[1], aLo[1]);
            bfsplit2(sf[2 * fk + 1][0], sf[2 * fk + 1][1], aHi[2], aLo[2]);
            bfsplit2(sf[2 * fk + 1][2], sf[2 * fk + 1][3], aHi[3], aLo[3]);
            uint32_t vh[8][2], vl[8][2];
            #pragma unroll
            for (int p = 0; p < 4; ++p) {
                uint32_t r0[4], r1[4];
                const uint32_t ra = kst + 18432 + (uint32_t)(fk * 16) * AROWB
                                  + laneBT + p * 32;
                ldm_x4_t(r0, ra);
                ldm_x4_t(r1, ra + 9216);
                vh[p * 2 + 0][0] = r0[0]; vh[p * 2 + 0][1] = r0[1];
                vh[p * 2 + 1][0] = r0[2]; vh[p * 2 + 1][1] = r0[3];
                vl[p * 2 + 0][0] = r1[0]; vl[p * 2 + 0][1] = r1[1];
                vl[p * 2 + 1][0] = r1[2]; vl[p * 2 + 1][1] = r1[3];
            }
            #pragma unroll
            for (int nf = 0; nf < 8; ++nf) {
                mma16816(of[nf], aHi, vh[nf]);
                mma16816(of[nf], aHi, vl[nf]);
                mma16816(of[nf], aLo, vh[nf]);
            }
        }

        __syncthreads();
        if (tile + 3 < 32) LOADKV(tile + 3, s);
        cp_commit();
    }

    const float iA = 1.0f / lA, iB = 1.0f / lB;
    const int rA = lane >> 2;
    const int rowA = tokb + q0 + w * 16 + rA;
    #pragma unroll
    for (int nf = 0; nf < 8; ++nf) {
        const int col = colb + nf * 8 + c0;
        uint32_t h0, l0, h1, l1;
        bfsplit2(of[nf][0] * iA, of[nf][1] * iA, h0, l0);
        bfsplit2(of[nf][2] * iB, of[nf][3] * iB, h1, l1);
        *(uint32_t*)&Yhi[(size_t)rowA * 1024 + col]       = h0;
        *(uint32_t*)&Ylo[(size_t)rowA * 1024 + col]       = l0;
        *(uint32_t*)&Yhi[(size_t)(rowA + 8) * 1024 + col] = h1;
        *(uint32_t*)&Ylo[(size_t)(rowA + 8) * 1024 + col] = l1;
    }
}

// ---------------------------------------------------------------------------
// LayerNorm: one row per CTA; optional fused bf16 hi/lo split output
// ---------------------------------------------------------------------------
__global__ __launch_bounds__(256)
void ln_kernel(const float* __restrict__ X, const float* __restrict__ w,
               const float* __restrict__ b, float* __restrict__ out,
               unsigned short* __restrict__ hi, unsigned short* __restrict__ lo)
{
    __shared__ float red[2][8];
    const int t = threadIdx.x;
    const size_t row = blockIdx.x;
    float4 xv = *(const float4*)&X[row * 1024 + t * 4];
    float s  = xv.x + xv.y + xv.z + xv.w;
    float s2 = xv.x * xv.x + xv.y * xv.y + xv.z * xv.z + xv.w * xv.w;
    #pragma unroll
    for (int off = 16; off; off >>= 1) {
        s  += __shfl_xor_sync(0xffffffffu, s,  off);
        s2 += __shfl_xor_sync(0xffffffffu, s2, off);
    }
    if ((t & 31) == 0) { red[0][t >> 5] = s; red[1][t >> 5] = s2; }
    __syncthreads();
    float S = 0.0f, S2 = 0.0f;
    #pragma unroll
    for (int i = 0; i < 8; ++i) { S += red[0][i]; S2 += red[1][i]; }
    const float mean = S * (1.0f / 1024.0f);
    const float var  = S2 * (1.0f / 1024.0f) - mean * mean;
    const float rstd = rsqrtf(var + 1e-5f);
    float4 wv = *(const float4*)&w[t * 4];
    float4 bv = *(const float4*)&b[t * 4];
    float4 r;
    r.x = (xv.x - mean) * rstd * wv.x + bv.x;
    r.y = (xv.y - mean) * rstd * wv.y + bv.y;
    r.z = (xv.z - mean) * rstd * wv.z + bv.z;
    r.w = (xv.w - mean) * rstd * wv.w + bv.w;
    if (out) *(float4*)&out[row * 1024 + t * 4] = r;
    if (hi) {
        uint32_t h0, l0, h1, l1;
        bfsplit2(r.x, r.y, h0, l0);
        bfsplit2(r.z, r.w, h1, l1);
        uint2 hv = make_uint2(h0, h1), lv = make_uint2(l0, l1);
        *(uint2*)&hi[row * 1024 + t * 4] = hv;
        *(uint2*)&lo[row * 1024 + t * 4] = lv;
    }
}

// ---------------------------------------------------------------------------
// launch
// ---------------------------------------------------------------------------
extern "C" void kernel_launch(void* const* d_in, const int* in_sizes, int n_in,
                              void* d_out, int out_size)
{
    (void)in_sizes; (void)n_in; (void)out_size;
    const float* x    = (const float*)d_in[0];
    const int*   mask = (const int*)  d_in[1];
    const float* WQ   = (const float*)d_in[2];
    const float* bQ   = (const float*)d_in[3];
    const float* WK   = (const float*)d_in[4];
    const float* bK   = (const float*)d_in[5];
    const float* WV   = (const float*)d_in[6];
    const float* bV   = (const float*)d_in[7];
    const float* WY   = (const float*)d_in[8];
    const float* bY   = (const float*)d_in[9];
    const float* ln1w = (const float*)d_in[10];
    const float* ln1b = (const float*)d_in[11];
    const float* ln2w = (const float*)d_in[12];
    const float* ln2b = (const float*)d_in[13];
    const float* W1   = (const float*)d_in[14];
    const float* b1   = (const float*)d_in[15];
    const float* W2   = (const float*)d_in[16];
    const float* b2   = (const float*)d_in[17];
    float* out = (float*)d_out;

    float *Qp, *Kp, *Vp, *Yp;
    unsigned short *Ahi, *Alo, *Whi, *Wlo;
    unsigned short *Qhi, *Qlo, *Khi, *Klo, *Vhi, *Vlo;
    cudaGetSymbolAddress((void**)&Qp,  g_Q);
    cudaGetSymbolAddress((void**)&Kp,  g_K);
    cudaGetSymbolAddress((void**)&Vp,  g_V);
    cudaGetSymbolAddress((void**)&Yp,  g_Y);
    cudaGetSymbolAddress((void**)&Ahi, g_Ahi);
    cudaGetSymbolAddress((void**)&Alo, g_Alo);
    cudaGetSymbolAddress((void**)&Whi, g_Whi);
    cudaGetSymbolAddress((void**)&Wlo, g_Wlo);
    cudaGetSymbolAddress((void**)&Qhi, g_Qhi);
    cudaGetSymbolAddress((void**)&Qlo, g_Qlo);
    cudaGetSymbolAddress((void**)&Khi, g_Khi);
    cudaGetSymbolAddress((void**)&Klo, g_Klo);
    cudaGetSymbolAddress((void**)&Vhi, g_Vhi);
    cudaGetSymbolAddress((void**)&Vlo, g_Vlo);

    unsigned short* Yhi = (unsigned short*)Yp;
    unsigned short* Ylo = (unsigned short*)Yp + (size_t)4096 * 1024;

    const size_t MB = (size_t)1024 * 1024;

    cudaFuncSetAttribute(tgemm_kernel<0>,
                         cudaFuncAttributeMaxDynamicSharedMemorySize, TG_SMEM);
    cudaFuncSetAttribute(tgemm_kernel<1>,
                         cudaFuncAttributeMaxDynamicSharedMemorySize, TG_SMEM);
    cudaFuncSetAttribute(tgemm_kernel<2>,
                         cudaFuncAttributeMaxDynamicSharedMemorySize, TG_SMEM);
    cudaFuncSetAttribute(attn_mma_kernel,
                         cudaFuncAttributeMaxDynamicSharedMemorySize, ATT_SMEM);

    dim3 blk(256);
    dim3 tsb(32, 8);

    // weight transposes
    tsplit_kernel<<<dim3(32, 32, 4), tsb>>>(WQ, WK, WV, WY, Whi, Wlo, MB, 1024, 1024);
    tsplit_kernel<<<dim3(128, 32, 1), tsb>>>(W1, W1, W1, W1, Whi + 4 * MB, Wlo + 4 * MB,
                                             0, 1024, 4096);
    tsplit_kernel<<<dim3(32, 128, 1), tsb>>>(W2, W2, W2, W2, Whi + 8 * MB, Wlo + 8 * MB,
                                             0, 4096, 1024);

    // x split
    split_kernel<<<4096, blk>>>(x, Ahi, Alo, (4096 * 1024) / 4);

    // QKV: all three outputs as bf16 splits (V natural layout, no fp32)
    tgemm_kernel<0><<<dim3(8, 32, 3), blk, TG_SMEM>>>(
        Ahi, Alo, Whi, Wlo, MB, bQ, bK, bV, nullptr,
        nullptr, nullptr, nullptr,
        Qhi, Khi, Vhi,
        Qlo, Klo, Vlo,
        4096, 1024, 1024);

    // attention -> Yhi/Ylo bf16
    attn_mma_kernel<<<dim3(16, 32), blk, ATT_SMEM>>>(
        Qhi, Qlo, Khi, Klo, Vhi, Vlo, mask, Yhi, Ylo);

    // out-proj + residual x -> fp32 g_Q
    tgemm_kernel<2><<<dim3(8, 32, 1), blk, TG_SMEM>>>(
        Yhi, Ylo, Whi + 3 * MB, Wlo + 3 * MB, 0, bY, bY, bY, x,
        Qp, nullptr, nullptr,
        nullptr, nullptr, nullptr,
        nullptr, nullptr, nullptr,
        4096, 1024, 1024);

    // h = LN1 -> fp32 g_K + bf16 split (Qhi/Qlo reused)
    ln_kernel<<<4096, blk>>>(Qp, ln1w, ln1b, Kp, Qhi, Qlo);

    // FFN1: gelu(h@W1+b1) -> bf16 split only
    tgemm_kernel<1><<<dim3(32, 32, 1), blk, TG_SMEM>>>(
        Qhi, Qlo, Whi + 4 * MB, Wlo + 4 * MB, 0, b1, b1, b1, nullptr,
        nullptr, nullptr, nullptr,
        Ahi, nullptr, nullptr,
        Alo, nullptr, nullptr,
        4096, 4096, 1024);

    // FFN2: ff@W2+b2+h -> fp32 g_V
    tgemm_kernel<2><<<dim3(8, 32, 1), blk, TG_SMEM>>>(
        Ahi, Alo, Whi + 8 * MB, Wlo + 8 * MB, 0, b2, b2, b2, Kp,
        Vp, nullptr, nullptr,
        nullptr, nullptr, nullptr,
        nullptr, nullptr, nullptr,
        4096, 1024, 4096);

    // out = LN2
    ln_kernel<<<4096, blk>>>(Vp, ln2w, ln2b, out, nullptr, nullptr);
}

// round 8
// speedup vs baseline: 1.0548x; 1.0548x over previous
#include <cuda_runtime.h>
#include <cuda_bf16.h>
#include <math.h>
#include <stdint.h>

// ---------------------------------------------------------------------------
// Scratch (__device__ globals; no allocations allowed)
// ---------------------------------------------------------------------------
__device__ float g_Q [(size_t)4096 * 1024];   // out-proj result (a+x)
__device__ float g_K [(size_t)4096 * 1024];   // h = LN1(...)
__device__ float g_V [(size_t)4096 * 1024];   // ffn2 result fp32
__device__ float g_Y [(size_t)4096 * 1024];   // Yhi/Ylo bf16 halves
__device__ unsigned short g_Ahi[(size_t)4096 * 4096];
__device__ unsigned short g_Alo[(size_t)4096 * 4096];
__device__ unsigned short g_Whi[(size_t)12 * 1024 * 1024];
__device__ unsigned short g_Wlo[(size_t)12 * 1024 * 1024];
__device__ unsigned short g_Qhi [(size_t)4096 * 1024];
__device__ unsigned short g_Qlo [(size_t)4096 * 1024];
__device__ unsigned short g_Khi [(size_t)4096 * 1024];
__device__ unsigned short g_Klo [(size_t)4096 * 1024];
__device__ unsigned short g_Vhi [(size_t)4096 * 1024];  // V natural layout
__device__ unsigned short g_Vlo [(size_t)4096 * 1024];

__device__ __forceinline__ uint32_t smem_u32(const void* p) {
    uint32_t a;
    asm("{ .reg .u64 t; cvta.to.shared.u64 t, %1; cvt.u32.u64 %0, t; }"
        : "=r"(a) : "l"(p));
    return a;
}
__device__ __forceinline__ void cpa16(uint32_t s, const void* g) {
    asm volatile("cp.async.cg.shared.global [%0], [%1], 16;"
                 :: "r"(s), "l"(__cvta_generic_to_global(g)) : "memory");
}
__device__ __forceinline__ void cp_commit() {
    asm volatile("cp.async.commit_group;" ::: "memory");
}
template<int N>
__device__ __forceinline__ void cp_wait() {
    asm volatile("cp.async.wait_group %0;" :: "n"(N) : "memory");
}
__device__ __forceinline__ void ldm_x4(uint32_t* r, uint32_t saddr) {
    asm volatile("ldmatrix.sync.aligned.m8n8.x4.shared.b16 {%0,%1,%2,%3}, [%4];"
                 : "=r"(r[0]), "=r"(r[1]), "=r"(r[2]), "=r"(r[3]) : "r"(saddr));
}
__device__ __forceinline__ void ldm_x4_t(uint32_t* r, uint32_t saddr) {
    asm volatile("ldmatrix.sync.aligned.m8n8.x4.trans.shared.b16 {%0,%1,%2,%3}, [%4];"
                 : "=r"(r[0]), "=r"(r[1]), "=r"(r[2]), "=r"(r[3]) : "r"(saddr));
}
__device__ __forceinline__ void mma16816(float* c, const uint32_t* a, const uint32_t* b) {
    asm volatile("mma.sync.aligned.m16n8k16.row.col.f32.bf16.bf16.f32 "
                 "{%0,%1,%2,%3}, {%4,%5,%6,%7}, {%8,%9}, {%0,%1,%2,%3};"
                 : "+f"(c[0]), "+f"(c[1]), "+f"(c[2]), "+f"(c[3])
                 : "r"(a[0]), "r"(a[1]), "r"(a[2]), "r"(a[3]),
                   "r"(b[0]), "r"(b[1]));
}
__device__ __forceinline__ float gelu_f(float v) {
    return 0.5f * v * (1.0f + erff(v * 0.70710678118654752f));
}
__device__ __forceinline__ void bfsplit2(float x, float y, uint32_t& hi, uint32_t& lo) {
    __nv_bfloat16 hx = __float2bfloat16(x), hy = __float2bfloat16(y);
    hi = ((uint32_t)(*(unsigned short*)&hy) << 16) | (uint32_t)(*(unsigned short*)&hx);
    __nv_bfloat16 lx = __float2bfloat16(x - __bfloat162float(hx));
    __nv_bfloat16 ly = __float2bfloat16(y - __bfloat162float(hy));
    lo = ((uint32_t)(*(unsigned short*)&ly) << 16) | (uint32_t)(*(unsigned short*)&lx);
}

// ---------------------------------------------------------------------------
// Tensor-core dense GEMM (R6 configuration: k-chunk 32, 3-stage, ROWB 80).
// C = (Ahi+Alo)[M,K] @ (Whi+Wlo)[N,K]^T (+bias | +bias,gelu | +bias+residual)
// Outputs per z: optional fp32 Cf, optional bf16 hi/lo (Ch/Cl).
// ---------------------------------------------------------------------------
#define ROWB   80
#define TILEB  (128 * ROWB)
#define STAGEB (4 * TILEB)
#define NSTAGE 3
#define TG_SMEM (NSTAGE * STAGEB)

template<int EPI>
__global__ __launch_bounds__(256, 1)
void tgemm_kernel(const unsigned short* __restrict__ Ahi16,
                  const unsigned short* __restrict__ Alo16,
                  const unsigned short* __restrict__ Whi16,
                  const unsigned short* __restrict__ Wlo16,
                  size_t wz,
                  const float* __restrict__ bias0, const float* __restrict__ bias1,
                  const float* __restrict__ bias2,
                  const float* __restrict__ R,
                  float* __restrict__ Cf0, float* __restrict__ Cf1, float* __restrict__ Cf2,
                  unsigned short* __restrict__ Ch0, unsigned short* __restrict__ Ch1,
                  unsigned short* __restrict__ Ch2,
                  unsigned short* __restrict__ Cl0, unsigned short* __restrict__ Cl1,
                  unsigned short* __restrict__ Cl2,
                  int M, int N, int K)
{
    extern __shared__ __align__(128) char smem[];
    const int z = blockIdx.z;
    const unsigned short* Bh = Whi16 + wz * z;
    const unsigned short* Bl = Wlo16 + wz * z;
    const float* bias = (z == 0) ? bias0 : (z == 1) ? bias1 : bias2;
    float*          Cf = (z == 0) ? Cf0 : (z == 1) ? Cf1 : Cf2;
    unsigned short* Ch = (z == 0) ? Ch0 : (z == 1) ? Ch1 : Ch2;
    unsigned short* Cl = (z == 0) ? Cl0 : (z == 1) ? Cl1 : Cl2;

    const uint32_t sbase = smem_u32(smem);
    const int t    = threadIdx.x;
    const int wid  = t >> 5;
    const int lane = t & 31;
    const int m0   = blockIdx.y * 128;
    const int n0   = blockIdx.x * 128;
    const int wm   = (wid & 1) * 64;
    const int wn   = (wid >> 1) * 32;

    const int lrow = t >> 1;
    const int lu   = (t & 1) * 2;
    const unsigned short* pAh = Ahi16 + (size_t)(m0 + lrow) * K + lu * 8;
    const unsigned short* pAl = Alo16 + (size_t)(m0 + lrow) * K + lu * 8;
    const unsigned short* pBh = Bh    + (size_t)(n0 + lrow) * K + lu * 8;
    const unsigned short* pBl = Bl    + (size_t)(n0 + lrow) * K + lu * 8;
    const uint32_t sRow = (uint32_t)lrow * ROWB + lu * 16;

    #define LOAD_STAGE(cc, ss) do {                                        \
        const uint32_t sb_ = sbase + (ss) * STAGEB + sRow;                  \
        const size_t  ko_ = (size_t)(cc) * 32;                              \
        cpa16(sb_ + 0 * TILEB,      pAh + ko_);                             \
        cpa16(sb_ + 0 * TILEB + 16, pAh + ko_ + 8);                         \
        cpa16(sb_ + 1 * TILEB,      pAl + ko_);                             \
        cpa16(sb_ + 1 * TILEB + 16, pAl + ko_ + 8);                         \
        cpa16(sb_ + 2 * TILEB,      pBh + ko_);                             \
        cpa16(sb_ + 2 * TILEB + 16, pBh + ko_ + 8);                         \
        cpa16(sb_ + 3 * TILEB,      pBl + ko_);                             \
        cpa16(sb_ + 3 * TILEB + 16, pBl + ko_ + 8);                         \
    } while (0)

    const uint32_t laneA = (uint32_t)(lane & 15) * ROWB + (lane >> 4) * 16;
    const uint32_t laneB = (uint32_t)((lane & 7) + ((lane >> 4) << 3)) * ROWB
                         + ((lane >> 3) & 1) * 16;

    float acc[4][4][4];
    #pragma unroll
    for (int i = 0; i < 4; ++i)
        #pragma unroll
        for (int j = 0; j < 4; ++j)
            #pragma unroll
            for (int q = 0; q < 4; ++q) acc[i][j][q] = 0.0f;

    const int NC = K >> 5;
    LOAD_STAGE(0, 0); cp_commit();
    LOAD_STAGE(1, 1); cp_commit();

    for (int c = 0; c < NC; ++c) {
        const int s = c % NSTAGE;
        cp_wait<1>();
        __syncthreads();
        if (c + 2 < NC) LOAD_STAGE(c + 2, (c + 2) % NSTAGE);
        cp_commit();

        const uint32_t stg = sbase + s * STAGEB;
        #pragma unroll
        for (int ks = 0; ks < 2; ++ks) {
            const uint32_t kb = ks * 32;
            uint32_t ah[4][4], al[4][4], bh[4][2], bl[4][2];
            #pragma unroll
            for (int mf = 0; mf < 4; ++mf) {
                const uint32_t ra = stg + (uint32_t)(wm + mf * 16) * ROWB + laneA + kb;
                ldm_x4(ah[mf], ra + 0 * TILEB);
                ldm_x4(al[mf], ra + 1 * TILEB);
            }
            #pragma unroll
            for (int p = 0; p < 2; ++p) {
                uint32_t rb[4], rl[4];
                const uint32_t ra = stg + (uint32_t)(wn + p * 16) * ROWB + laneB + kb;
                ldm_x4(rb, ra + 2 * TILEB);
                ldm_x4(rl, ra + 3 * TILEB);
                bh[p * 2 + 0][0] = rb[0]; bh[p * 2 + 0][1] = rb[1];
                bh[p * 2 + 1][0] = rb[2]; bh[p * 2 + 1][1] = rb[3];
                bl[p * 2 + 0][0] = rl[0]; bl[p * 2 + 0][1] = rl[1];
                bl[p * 2 + 1][0] = rl[2]; bl[p * 2 + 1][1] = rl[3];
            }
            #pragma unroll
            for (int mf = 0; mf < 4; ++mf)
                #pragma unroll
                for (int nf = 0; nf < 4; ++nf) {
                    mma16816(acc[mf][nf], ah[mf], bh[nf]);
                    mma16816(acc[mf][nf], ah[mf], bl[nf]);
                    mma16816(acc[mf][nf], al[mf], bh[nf]);
                }
        }
    }

    const int rbase = lane >> 2;
    const int cbase = (lane & 3) * 2;
    #pragma unroll
    for (int mf = 0; mf < 4; ++mf) {
        #pragma unroll
        for (int nf = 0; nf < 4; ++nf) {
            const int col = n0 + wn + nf * 8 + cbase;
            const float2 bb = *(const float2*)&bias[col];
            #pragma unroll
            for (int h = 0; h < 2; ++h) {
                const int row = m0 + wm + mf * 16 + rbase + h * 8;
                float2 rv;
                rv.x = acc[mf][nf][h * 2 + 0] + bb.x;
                rv.y = acc[mf][nf][h * 2 + 1] + bb.y;
                if (EPI == 1) { rv.x = gelu_f(rv.x); rv.y = gelu_f(rv.y); }
                if (EPI == 2) {
                    const float2 rr = *(const float2*)&R[(size_t)row * N + col];
                    rv.x += rr.x; rv.y += rr.y;
                }
                if (Cf) *(float2*)&Cf[(size_t)row * N + col] = rv;
                if (Ch) {
                    uint32_t hi, lo;
                    bfsplit2(rv.x, rv.y, hi, lo);
                    *(uint32_t*)&Ch[(size_t)row * N + col] = hi;
                    *(uint32_t*)&Cl[(size_t)row * N + col] = lo;
                }
            }
        }
    }
    #undef LOAD_STAGE
}

// ---------------------------------------------------------------------------
// fp32 -> bf16 hi/lo split kernels
// ---------------------------------------------------------------------------
__device__ __forceinline__ void split1(float v, unsigned short& h, unsigned short& l) {
    __nv_bfloat16 hb = __float2bfloat16(v);
    __nv_bfloat16 lb = __float2bfloat16(v - __bfloat162float(hb));
    h = *(unsigned short*)&hb;
    l = *(unsigned short*)&lb;
}

__global__ __launch_bounds__(256)
void split_kernel(const float* __restrict__ X, unsigned short* __restrict__ hi,
                  unsigned short* __restrict__ lo, int n4)
{
    int i = blockIdx.x * 256 + threadIdx.x;
    if (i >= n4) return;
    float4 v = ((const float4*)X)[i];
    ushort4 h, l;
    split1(v.x, h.x, l.x); split1(v.y, h.y, l.y);
    split1(v.z, h.z, l.z); split1(v.w, h.w, l.w);
    ((ushort4*)hi)[i] = h;
    ((ushort4*)lo)[i] = l;
}

// transpose+split; z-fused for up to 4 equal-shaped weights
__global__ __launch_bounds__(256)
void tsplit_kernel(const float* __restrict__ W0, const float* __restrict__ W1,
                   const float* __restrict__ W2, const float* __restrict__ W3,
                   unsigned short* __restrict__ Thi, unsigned short* __restrict__ Tlo,
                   size_t zstride, int K, int N)
{
    __shared__ float s[32][33];
    const int z = blockIdx.z;
    const float* W = (z == 0) ? W0 : (z == 1) ? W1 : (z == 2) ? W2 : W3;
    unsigned short* Th = Thi + zstride * z;
    unsigned short* Tl = Tlo + zstride * z;
    const int tx = threadIdx.x, ty = threadIdx.y;
    const int nb = blockIdx.x * 32, kb = blockIdx.y * 32;
    #pragma unroll
    for (int i = 0; i < 4; ++i)
        s[ty + i * 8][tx] = W[(size_t)(kb + ty + i * 8) * N + nb + tx];
    __syncthreads();
    #pragma unroll
    for (int i = 0; i < 4; ++i) {
        const float v = s[tx][ty + i * 8];
        unsigned short h, l;
        split1(v, h, l);
        const size_t o = (size_t)(nb + ty + i * 8) * K + kb + tx;
        Th[o] = h; Tl[o] = l;
    }
}

// ---------------------------------------------------------------------------
// Flash attention via mma.sync; V in NATURAL layout via ldmatrix.trans.
// 2-stage KV pipeline (R6 structure). Output written directly as bf16 hi/lo.
// ---------------------------------------------------------------------------
#define AROWB   144
#define ATT_QLO 18432
#define ATT_KV  36864
#define ATT_STG 36864
#define ATT_MB  (ATT_KV + 2 * ATT_STG)
#define ATT_SMEM (ATT_MB + 512)

__global__ __launch_bounds__(256, 1)
void attn_mma_kernel(const unsigned short* __restrict__ Qhi,
                     const unsigned short* __restrict__ Qlo,
                     const unsigned short* __restrict__ Khi,
                     const unsigned short* __restrict__ Klo,
                     const unsigned short* __restrict__ Vhi,
                     const unsigned short* __restrict__ Vlo,
                     const int* __restrict__ mask,
                     unsigned short* __restrict__ Yhi,
                     unsigned short* __restrict__ Ylo)
{
    extern __shared__ __align__(128) char smem[];
    const uint32_t sb = smem_u32(smem);
    const int t    = threadIdx.x;
    const int lane = t & 31;
    const int w    = t >> 5;
    const int q0   = blockIdx.x * 128;
    const int bh   = blockIdx.y;
    const int tokb = (bh >> 4) * 2048;
    const int colb = (bh & 15) * 64;

    const uint32_t laneA = (uint32_t)(lane & 15) * AROWB + (lane >> 4) * 16;
    const uint32_t laneB = (uint32_t)((lane & 7) + ((lane >> 4) << 3)) * AROWB
                         + ((lane >> 3) & 1) * 16;
    // trans lane map for V (natural layout): B-fragment via ldmatrix.trans
    const uint32_t laneBT = (uint32_t)((lane & 7) + ((lane >> 3) & 1) * 8) * AROWB
                          + (lane >> 4) * 16;

    {
        const int row = t >> 1;
        const size_t g = (size_t)(tokb + q0 + row) * 1024 + colb;
        const uint32_t sr = (uint32_t)row * AROWB;
        #pragma unroll
        for (int i = 0; i < 4; ++i) {
            const int ch = (t & 1) * 4 + i;
            cpa16(sb + sr + ch * 16,           Qhi + g + ch * 8);
            cpa16(sb + ATT_QLO + sr + ch * 16, Qlo + g + ch * 8);
        }
    }

    auto LOADKV = [&](int tile, int s) {
        const int kv0 = tile * 64;
        const int row = t >> 2;
        const int q2  = t & 3;
        const uint32_t st = sb + ATT_KV + s * ATT_STG;
        const size_t gk = (size_t)(tokb + kv0 + row) * 1024 + colb;
        const uint32_t sr = (uint32_t)row * AROWB;
        #pragma unroll
        for (int i = 0; i < 2; ++i) {
            const int ch = q2 * 2 + i;
            cpa16(st +         sr + ch * 16, Khi + gk + ch * 8);
            cpa16(st +  9216 + sr + ch * 16, Klo + gk + ch * 8);
            cpa16(st + 18432 + sr + ch * 16, Vhi + gk + ch * 8);
            cpa16(st + 27648 + sr + ch * 16, Vlo + gk + ch * 8);
        }
        if (t < 64) {
            float* mb = (float*)(smem + ATT_MB) + s * 64;
            mb[t] = (mask[tokb + kv0 + t] == 0) ? -1e30f : 0.0f;
        }
    };

    LOADKV(0, 0); cp_commit();
    LOADKV(1, 1); cp_commit();

    cp_wait<1>();
    __syncthreads();

    uint32_t qh[4][4], ql[4][4];
    #pragma unroll
    for (int fk = 0; fk < 4; ++fk) {
        const uint32_t ra = sb + (uint32_t)(w * 16) * AROWB + laneA + fk * 32;
        ldm_x4(qh[fk], ra);
        ldm_x4(ql[fk], ra + ATT_QLO);
    }

    float of[8][4];
    #pragma unroll
    for (int i = 0; i < 8; ++i)
        #pragma unroll
        for (int j = 0; j < 4; ++j) of[i][j] = 0.0f;
    float mA = -1e30f, mB = -1e30f, lA = 0.0f, lB = 0.0f;
    const int c0 = (lane & 3) * 2;

    for (int tile = 0; tile < 32; ++tile) {
        const int s = tile & 1;
        if (tile > 0) { cp_wait<1>(); __syncthreads(); }
        const uint32_t kst = sb + ATT_KV + s * ATT_STG;
        const float* mb = (const float*)(smem + ATT_MB) + s * 64;

        float sf[8][4];
        #pragma unroll
        for (int i = 0; i < 8; ++i)
            #pragma unroll
            for (int j = 0; j < 4; ++j) sf[i][j] = 0.0f;

        #pragma unroll
        for (int fk = 0; fk < 4; ++fk) {
            uint32_t kh[8][2], kl[8][2];
            #pragma unroll
            for (int p = 0; p < 4; ++p) {
                uint32_t r0[4], r1[4];
                const uint32_t ra = kst + (uint32_t)(p * 16) * AROWB + laneB + fk * 32;
                ldm_x4(r0, ra);
                ldm_x4(r1, ra + 9216);
                kh[p * 2 + 0][0] = r0[0]; kh[p * 2 + 0][1] = r0[1];
                kh[p * 2 + 1][0] = r0[2]; kh[p * 2 + 1][1] = r0[3];
                kl[p * 2 + 0][0] = r1[0]; kl[p * 2 + 0][1] = r1[1];
                kl[p * 2 + 1][0] = r1[2]; kl[p * 2 + 1][1] = r1[3];
            }
            #pragma unroll
            for (int nf = 0; nf < 8; ++nf) {
                mma16816(sf[nf], qh[fk], kh[nf]);
                mma16816(sf[nf], qh[fk], kl[nf]);
                mma16816(sf[nf], ql[fk], kh[nf]);
            }
        }

        float pmA = -1e30f, pmB = -1e30f;
        #pragma unroll
        for (int nf = 0; nf < 8; ++nf) {
            const float m0 = mb[nf * 8 + c0];
            const float m1 = mb[nf * 8 + c0 + 1];
            sf[nf][0] = fmaf(sf[nf][0], 0.125f, m0);
            sf[nf][1] = fmaf(sf[nf][1], 0.125f, m1);
            sf[nf][2] = fmaf(sf[nf][2], 0.125f, m0);
            sf[nf][3] = fmaf(sf[nf][3], 0.125f, m1);
            pmA = fmaxf(pmA, fmaxf(sf[nf][0], sf[nf][1]));
            pmB = fmaxf(pmB, fmaxf(sf[nf][2], sf[nf][3]));
        }
        pmA = fmaxf(pmA, __shfl_xor_sync(0xffffffffu, pmA, 1));
        pmA = fmaxf(pmA, __shfl_xor_sync(0xffffffffu, pmA, 2));
        pmB = fmaxf(pmB, __shfl_xor_sync(0xffffffffu, pmB, 1));
        pmB = fmaxf(pmB, __shfl_xor_sync(0xffffffffu, pmB, 2));
        const float mnA = fmaxf(mA, pmA), mnB = fmaxf(mB, pmB);
        const float alA = __expf(mA - mnA), alB = __expf(mB - mnB);
        mA = mnA; mB = mnB;
        float rsA = 0.0f, rsB = 0.0f;
        #pragma unroll
        for (int nf = 0; nf < 8; ++nf) {
            sf[nf][0] = __expf(sf[nf][0] - mnA);
            sf[nf][1] = __expf(sf[nf][1] - mnA);
            sf[nf][2] = __expf(sf[nf][2] - mnB);
            sf[nf][3] = __expf(sf[nf][3] - mnB);
            rsA += sf[nf][0] + sf[nf][1];
            rsB += sf[nf][2] + sf[nf][3];
        }
        rsA += __shfl_xor_sync(0xffffffffu, rsA, 1);
        rsA += __shfl_xor_sync(0xffffffffu, rsA, 2);
        rsB += __shfl_xor_sync(0xffffffffu, rsB, 1);
        rsB += __shfl_xor_sync(0xffffffffu, rsB, 2);
        lA = lA * alA + rsA;
        lB = lB * alB + rsB;
        #pragma unroll
        for (int nf = 0; nf < 8; ++nf) {
            of[nf][0] *= alA; of[nf][1] *= alA;
            of[nf][2] *= alB; of[nf][3] *= alB;
        }

        // O += (Phi+Plo) @ V, V natural layout via ldmatrix.trans
        #pragma unroll
        for (int fk = 0; fk < 4; ++fk) {
            uint32_t aHi[4], aLo[4];
            bfsplit2(sf[2 * fk][0],     sf[2 * fk][1],     aHi[0], aLo[0]);
            bfsplit2(sf[2 * fk][2],     sf[2 * fk][3],     aHi[1], aLo[1]);
            bfsplit2(sf[2 * fk + 1][0], sf[2 * fk + 1][1], aHi[2], aLo[2]);
            bfsplit2(sf[2 * fk + 1][2], sf[2 * fk + 1][3], aHi[3], aLo[3]);
            uint32_t vh[8][2], vl[8][2];
            #pragma unroll
            for (int p = 0; p < 4; ++p) {
                uint32_t r0[4], r1[4];
                const uint32_t ra = kst + 18432 + (uint32_t)(fk * 16) * AROWB
                                  + laneBT + p * 32;
                ldm_x4_t(r0, ra);
                ldm_x4_t(r1, ra + 9216);
                vh[p * 2 + 0][0] = r0[0]; vh[p * 2 + 0][1] = r0[1];
                vh[p * 2 + 1][0] = r0[2]; vh[p * 2 + 1][1] = r0[3];
                vl[p * 2 + 0][0] = r1[0]; vl[p * 2 + 0][1] = r1[1];
                vl[p * 2 + 1][0] = r1[2]; vl[p * 2 + 1][1] = r1[3];
            }
            #pragma unroll
            for (int nf = 0; nf < 8; ++nf) {
                mma16816(of[nf], aHi, vh[nf]);
                mma16816(of[nf], aHi, vl[nf]);
                mma16816(of[nf], aLo, vh[nf]);
            }
        }

        __syncthreads();
        if (tile + 2 < 32) LOADKV(tile + 2, s);
        cp_commit();
    }

    const float iA = 1.0f / lA, iB = 1.0f / lB;
    const int rA = lane >> 2;
    const int rowA = tokb + q0 + w * 16 + rA;
    #pragma unroll
    for (int nf = 0; nf < 8; ++nf) {
        const int col = colb + nf * 8 + c0;
        uint32_t h0, l0, h1, l1;
        bfsplit2(of[nf][0] * iA, of[nf][1] * iA, h0, l0);
        bfsplit2(of[nf][2] * iB, of[nf][3] * iB, h1, l1);
        *(uint32_t*)&Yhi[(size_t)rowA * 1024 + col]       = h0;
        *(uint32_t*)&Ylo[(size_t)rowA * 1024 + col]       = l0;
        *(uint32_t*)&Yhi[(size_t)(rowA + 8) * 1024 + col] = h1;
        *(uint32_t*)&Ylo[(size_t)(rowA + 8) * 1024 + col] = l1;
    }
}

// ---------------------------------------------------------------------------
// LayerNorm: one row per CTA; optional fused bf16 hi/lo split output
// ---------------------------------------------------------------------------
__global__ __launch_bounds__(256)
void ln_kernel(const float* __restrict__ X, const float* __restrict__ w,
               const float* __restrict__ b, float* __restrict__ out,
               unsigned short* __restrict__ hi, unsigned short* __restrict__ lo)
{
    __shared__ float red[2][8];
    const int t = threadIdx.x;
    const size_t row = blockIdx.x;
    float4 xv = *(const float4*)&X[row * 1024 + t * 4];
    float s  = xv.x + xv.y + xv.z + xv.w;
    float s2 = xv.x * xv.x + xv.y * xv.y + xv.z * xv.z + xv.w * xv.w;
    #pragma unroll
    for (int off = 16; off; off >>= 1) {
        s  += __shfl_xor_sync(0xffffffffu, s,  off);
        s2 += __shfl_xor_sync(0xffffffffu, s2, off);
    }
    if ((t & 31) == 0) { red[0][t >> 5] = s; red[1][t >> 5] = s2; }
    __syncthreads();
    float S = 0.0f, S2 = 0.0f;
    #pragma unroll
    for (int i = 0; i < 8; ++i) { S += red[0][i]; S2 += red[1][i]; }
    const float mean = S * (1.0f / 1024.0f);
    const float var  = S2 * (1.0f / 1024.0f) - mean * mean;
    const float rstd = rsqrtf(var + 1e-5f);
    float4 wv = *(const float4*)&w[t * 4];
    float4 bv = *(const float4*)&b[t * 4];
    float4 r;
    r.x = (xv.x - mean) * rstd * wv.x + bv.x;
    r.y = (xv.y - mean) * rstd * wv.y + bv.y;
    r.z = (xv.z - mean) * rstd * wv.z + bv.z;
    r.w = (xv.w - mean) * rstd * wv.w + bv.w;
    if (out) *(float4*)&out[row * 1024 + t * 4] = r;
    if (hi) {
        uint32_t h0, l0, h1, l1;
        bfsplit2(r.x, r.y, h0, l0);
        bfsplit2(r.z, r.w, h1, l1);
        uint2 hv = make_uint2(h0, h1), lv = make_uint2(l0, l1);
        *(uint2*)&hi[row * 1024 + t * 4] = hv;
        *(uint2*)&lo[row * 1024 + t * 4] = lv;
    }
}

// ---------------------------------------------------------------------------
// launch
// ---------------------------------------------------------------------------
extern "C" void kernel_launch(void* const* d_in, const int* in_sizes, int n_in,
                              void* d_out, int out_size)
{
    (void)in_sizes; (void)n_in; (void)out_size;
    const float* x    = (const float*)d_in[0];
    const int*   mask = (const int*)  d_in[1];
    const float* WQ   = (const float*)d_in[2];
    const float* bQ   = (const float*)d_in[3];
    const float* WK   = (const float*)d_in[4];
    const float* bK   = (const float*)d_in[5];
    const float* WV   = (const float*)d_in[6];
    const float* bV   = (const float*)d_in[7];
    const float* WY   = (const float*)d_in[8];
    const float* bY   = (const float*)d_in[9];
    const float* ln1w = (const float*)d_in[10];
    const float* ln1b = (const float*)d_in[11];
    const float* ln2w = (const float*)d_in[12];
    const float* ln2b = (const float*)d_in[13];
    const float* W1   = (const float*)d_in[14];
    const float* b1   = (const float*)d_in[15];
    const float* W2   = (const float*)d_in[16];
    const float* b2   = (const float*)d_in[17];
    float* out = (float*)d_out;

    float *Qp, *Kp, *Vp, *Yp;
    unsigned short *Ahi, *Alo, *Whi, *Wlo;
    unsigned short *Qhi, *Qlo, *Khi, *Klo, *Vhi, *Vlo;
    cudaGetSymbolAddress((void**)&Qp,  g_Q);
    cudaGetSymbolAddress((void**)&Kp,  g_K);
    cudaGetSymbolAddress((void**)&Vp,  g_V);
    cudaGetSymbolAddress((void**)&Yp,  g_Y);
    cudaGetSymbolAddress((void**)&Ahi, g_Ahi);
    cudaGetSymbolAddress((void**)&Alo, g_Alo);
    cudaGetSymbolAddress((void**)&Whi, g_Whi);
    cudaGetSymbolAddress((void**)&Wlo, g_Wlo);
    cudaGetSymbolAddress((void**)&Qhi, g_Qhi);
    cudaGetSymbolAddress((void**)&Qlo, g_Qlo);
    cudaGetSymbolAddress((void**)&Khi, g_Khi);
    cudaGetSymbolAddress((void**)&Klo, g_Klo);
    cudaGetSymbolAddress((void**)&Vhi, g_Vhi);
    cudaGetSymbolAddress((void**)&Vlo, g_Vlo);

    unsigned short* Yhi = (unsigned short*)Yp;
    unsigned short* Ylo = (unsigned short*)Yp + (size_t)4096 * 1024;

    const size_t MB = (size_t)1024 * 1024;

    cudaFuncSetAttribute(tgemm_kernel<0>,
                         cudaFuncAttributeMaxDynamicSharedMemorySize, TG_SMEM);
    cudaFuncSetAttribute(tgemm_kernel<1>,
                         cudaFuncAttributeMaxDynamicSharedMemorySize, TG_SMEM);
    cudaFuncSetAttribute(tgemm_kernel<2>,
                         cudaFuncAttributeMaxDynamicSharedMemorySize, TG_SMEM);
    cudaFuncSetAttribute(attn_mma_kernel,
                         cudaFuncAttributeMaxDynamicSharedMemorySize, ATT_SMEM);

    dim3 blk(256);
    dim3 tsb(32, 8);

    // weight transposes
    tsplit_kernel<<<dim3(32, 32, 4), tsb>>>(WQ, WK, WV, WY, Whi, Wlo, MB, 1024, 1024);
    tsplit_kernel<<<dim3(128, 32, 1), tsb>>>(W1, W1, W1, W1, Whi + 4 * MB, Wlo + 4 * MB,
                                             0, 1024, 4096);
    tsplit_kernel<<<dim3(32, 128, 1), tsb>>>(W2, W2, W2, W2, Whi + 8 * MB, Wlo + 8 * MB,
                                             0, 4096, 1024);

    // x split
    split_kernel<<<4096, blk>>>(x, Ahi, Alo, (4096 * 1024) / 4);

    // QKV: all three outputs as bf16 splits (V natural layout, no fp32)
    tgemm_kernel<0><<<dim3(8, 32, 3), blk, TG_SMEM>>>(
        Ahi, Alo, Whi, Wlo, MB, bQ, bK, bV, nullptr,
        nullptr, nullptr, nullptr,
        Qhi, Khi, Vhi,
        Qlo, Klo, Vlo,
        4096, 1024, 1024);

    // attention -> Yhi/Ylo bf16
    attn_mma_kernel<<<dim3(16, 32), blk, ATT_SMEM>>>(
        Qhi, Qlo, Khi, Klo, Vhi, Vlo, mask, Yhi, Ylo);

    // out-proj + residual x -> fp32 g_Q
    tgemm_kernel<2><<<dim3(8, 32, 1), blk, TG_SMEM>>>(
        Yhi, Ylo, Whi + 3 * MB, Wlo + 3 * MB, 0, bY, bY, bY, x,
        Qp, nullptr, nullptr,
        nullptr, nullptr, nullptr,
        nullptr, nullptr, nullptr,
        4096, 1024, 1024);

    // h = LN1 -> fp32 g_K + bf16 split (Qhi/Qlo reused)
    ln_kernel<<<4096, blk>>>(Qp, ln1w, ln1b, Kp, Qhi, Qlo);

    // FFN1: gelu(h@W1+b1) -> bf16 split only
    tgemm_kernel<1><<<dim3(32, 32, 1), blk, TG_SMEM>>>(
        Qhi, Qlo, Whi + 4 * MB, Wlo + 4 * MB, 0, b1, b1, b1, nullptr,
        nullptr, nullptr, nullptr,
        Ahi, nullptr, nullptr,
        Alo, nullptr, nullptr,
        4096, 4096, 1024);

    // FFN2: ff@W2+b2+h -> fp32 g_V
    tgemm_kernel<2><<<dim3(8, 32, 1), blk, TG_SMEM>>>(
        Ahi, Alo, Whi + 8 * MB, Wlo + 8 * MB, 0, b2, b2, b2, Kp,
        Vp, nullptr, nullptr,
        nullptr, nullptr, nullptr,
        nullptr, nullptr, nullptr,
        4096, 1024, 4096);

    // out = LN2
    ln_kernel<<<4096, blk>>>(Vp, ln2w, ln2b, out, nullptr, nullptr);
}

// round 9
// speedup vs baseline: 1.1264x; 1.0679x over previous
#include <cuda_runtime.h>
#include <cuda_bf16.h>
#include <math.h>
#include <stdint.h>

// ---------------------------------------------------------------------------
// Scratch (__device__ globals; no allocations allowed)
// ---------------------------------------------------------------------------
__device__ float g_Q [(size_t)4096 * 1024];   // out-proj result (a+x)
__device__ float g_K [(size_t)4096 * 1024];   // h = LN1(...)
__device__ float g_V [(size_t)4096 * 1024];   // ffn2 result fp32
__device__ float g_Y [(size_t)4096 * 1024];   // Yhi/Ylo bf16 halves
__device__ unsigned short g_Ahi[(size_t)4096 * 4096];
__device__ unsigned short g_Alo[(size_t)4096 * 4096];
__device__ unsigned short g_Whi[(size_t)12 * 1024 * 1024];
__device__ unsigned short g_Wlo[(size_t)12 * 1024 * 1024];
__device__ unsigned short g_Qhi [(size_t)4096 * 1024];
__device__ unsigned short g_Qlo [(size_t)4096 * 1024];
__device__ unsigned short g_Khi [(size_t)4096 * 1024];
__device__ unsigned short g_Klo [(size_t)4096 * 1024];
__device__ unsigned short g_Vhi [(size_t)4096 * 1024];  // V natural layout
__device__ unsigned short g_Vlo [(size_t)4096 * 1024];

__device__ __forceinline__ uint32_t smem_u32(const void* p) {
    uint32_t a;
    asm("{ .reg .u64 t; cvta.to.shared.u64 t, %1; cvt.u32.u64 %0, t; }"
        : "=r"(a) : "l"(p));
    return a;
}
__device__ __forceinline__ void cpa16(uint32_t s, const void* g) {
    asm volatile("cp.async.cg.shared.global [%0], [%1], 16;"
                 :: "r"(s), "l"(__cvta_generic_to_global(g)) : "memory");
}
__device__ __forceinline__ void cp_commit() {
    asm volatile("cp.async.commit_group;" ::: "memory");
}
template<int N>
__device__ __forceinline__ void cp_wait() {
    asm volatile("cp.async.wait_group %0;" :: "n"(N) : "memory");
}
__device__ __forceinline__ void ldm_x4(uint32_t* r, uint32_t saddr) {
    asm volatile("ldmatrix.sync.aligned.m8n8.x4.shared.b16 {%0,%1,%2,%3}, [%4];"
                 : "=r"(r[0]), "=r"(r[1]), "=r"(r[2]), "=r"(r[3]) : "r"(saddr));
}
__device__ __forceinline__ void ldm_x4_t(uint32_t* r, uint32_t saddr) {
    asm volatile("ldmatrix.sync.aligned.m8n8.x4.trans.shared.b16 {%0,%1,%2,%3}, [%4];"
                 : "=r"(r[0]), "=r"(r[1]), "=r"(r[2]), "=r"(r[3]) : "r"(saddr));
}
__device__ __forceinline__ void mma16816(float* c, const uint32_t* a, const uint32_t* b) {
    asm volatile("mma.sync.aligned.m16n8k16.row.col.f32.bf16.bf16.f32 "
                 "{%0,%1,%2,%3}, {%4,%5,%6,%7}, {%8,%9}, {%0,%1,%2,%3};"
                 : "+f"(c[0]), "+f"(c[1]), "+f"(c[2]), "+f"(c[3])
                 : "r"(a[0]), "r"(a[1]), "r"(a[2]), "r"(a[3]),
                   "r"(b[0]), "r"(b[1]));
}
__device__ __forceinline__ float gelu_f(float v) {
    return 0.5f * v * (1.0f + erff(v * 0.70710678118654752f));
}
__device__ __forceinline__ void bfsplit2(float x, float y, uint32_t& hi, uint32_t& lo) {
    __nv_bfloat16 hx = __float2bfloat16(x), hy = __float2bfloat16(y);
    hi = ((uint32_t)(*(unsigned short*)&hy) << 16) | (uint32_t)(*(unsigned short*)&hx);
    __nv_bfloat16 lx = __float2bfloat16(x - __bfloat162float(hx));
    __nv_bfloat16 ly = __float2bfloat16(y - __bfloat162float(hy));
    lo = ((uint32_t)(*(unsigned short*)&ly) << 16) | (uint32_t)(*(unsigned short*)&lx);
}

// ---------------------------------------------------------------------------
// Tensor-core dense GEMM. k-chunk 32, 2-stage pipeline, ROWB 80,
// 2 CTAs/SM (register-dieted inner loop: B frags persistent, A streamed).
// C = (Ahi+Alo)[M,K] @ (Whi+Wlo)[N,K]^T (+bias | +bias,gelu | +bias+residual)
// ---------------------------------------------------------------------------
#define ROWB   80
#define TILEB  (128 * ROWB)
#define STAGEB (4 * TILEB)
#define NSTAGE 2
#define TG_SMEM (NSTAGE * STAGEB)    // 81920 -> 2 CTAs/SM

template<int EPI>
__global__ __launch_bounds__(256, 2)
void tgemm_kernel(const unsigned short* __restrict__ Ahi16,
                  const unsigned short* __restrict__ Alo16,
                  const unsigned short* __restrict__ Whi16,
                  const unsigned short* __restrict__ Wlo16,
                  size_t wz,
                  const float* __restrict__ bias0, const float* __restrict__ bias1,
                  const float* __restrict__ bias2,
                  const float* __restrict__ R,
                  float* __restrict__ Cf0, float* __restrict__ Cf1, float* __restrict__ Cf2,
                  unsigned short* __restrict__ Ch0, unsigned short* __restrict__ Ch1,
                  unsigned short* __restrict__ Ch2,
                  unsigned short* __restrict__ Cl0, unsigned short* __restrict__ Cl1,
                  unsigned short* __restrict__ Cl2,
                  int M, int N, int K)
{
    extern __shared__ __align__(128) char smem[];
    const int z = blockIdx.z;
    const unsigned short* Bh = Whi16 + wz * z;
    const unsigned short* Bl = Wlo16 + wz * z;
    const float* bias = (z == 0) ? bias0 : (z == 1) ? bias1 : bias2;
    float*          Cf = (z == 0) ? Cf0 : (z == 1) ? Cf1 : Cf2;
    unsigned short* Ch = (z == 0) ? Ch0 : (z == 1) ? Ch1 : Ch2;
    unsigned short* Cl = (z == 0) ? Cl0 : (z == 1) ? Cl1 : Cl2;

    const uint32_t sbase = smem_u32(smem);
    const int t    = threadIdx.x;
    const int wid  = t >> 5;
    const int lane = t & 31;
    const int m0   = blockIdx.y * 128;
    const int n0   = blockIdx.x * 128;
    const int wm   = (wid & 1) * 64;
    const int wn   = (wid >> 1) * 32;

    const int lrow = t >> 1;
    const int lu   = (t & 1) * 2;
    const unsigned short* pAh = Ahi16 + (size_t)(m0 + lrow) * K + lu * 8;
    const unsigned short* pAl = Alo16 + (size_t)(m0 + lrow) * K + lu * 8;
    const unsigned short* pBh = Bh    + (size_t)(n0 + lrow) * K + lu * 8;
    const unsigned short* pBl = Bl    + (size_t)(n0 + lrow) * K + lu * 8;
    const uint32_t sRow = (uint32_t)lrow * ROWB + lu * 16;

    #define LOAD_STAGE(cc, ss) do {                                        \
        const uint32_t sb_ = sbase + (ss) * STAGEB + sRow;                  \
        const size_t  ko_ = (size_t)(cc) * 32;                              \
        cpa16(sb_ + 0 * TILEB,      pAh + ko_);                             \
        cpa16(sb_ + 0 * TILEB + 16, pAh + ko_ + 8);                         \
        cpa16(sb_ + 1 * TILEB,      pAl + ko_);                             \
        cpa16(sb_ + 1 * TILEB + 16, pAl + ko_ + 8);                         \
        cpa16(sb_ + 2 * TILEB,      pBh + ko_);                             \
        cpa16(sb_ + 2 * TILEB + 16, pBh + ko_ + 8);                         \
        cpa16(sb_ + 3 * TILEB,      pBl + ko_);                             \
        cpa16(sb_ + 3 * TILEB + 16, pBl + ko_ + 8);                         \
    } while (0)

    const uint32_t laneA = (uint32_t)(lane & 15) * ROWB + (lane >> 4) * 16;
    const uint32_t laneB = (uint32_t)((lane & 7) + ((lane >> 4) << 3)) * ROWB
                         + ((lane >> 3) & 1) * 16;

    float acc[4][4][4];
    #pragma unroll
    for (int i = 0; i < 4; ++i)
        #pragma unroll
        for (int j = 0; j < 4; ++j)
            #pragma unroll
            for (int q = 0; q < 4; ++q) acc[i][j][q] = 0.0f;

    const int NC = K >> 5;
    LOAD_STAGE(0, 0); cp_commit();

    for (int c = 0; c < NC; ++c) {
        const int s = c & 1;
        if (c + 1 < NC) LOAD_STAGE(c + 1, s ^ 1);
        cp_commit();
        cp_wait<1>();
        __syncthreads();

        const uint32_t stg = sbase + s * STAGEB;
        #pragma unroll
        for (int ks = 0; ks < 2; ++ks) {
            const uint32_t kb = ks * 32;
            // B fragments persistent (16 regs)
            uint32_t bh[4][2], bl[4][2];
            #pragma unroll
            for (int p = 0; p < 2; ++p) {
                uint32_t rb[4], rl[4];
                const uint32_t ra = stg + (uint32_t)(wn + p * 16) * ROWB + laneB + kb;
                ldm_x4(rb, ra + 2 * TILEB);
                ldm_x4(rl, ra + 3 * TILEB);
                bh[p * 2 + 0][0] = rb[0]; bh[p * 2 + 0][1] = rb[1];
                bh[p * 2 + 1][0] = rb[2]; bh[p * 2 + 1][1] = rb[3];
                bl[p * 2 + 0][0] = rl[0]; bl[p * 2 + 0][1] = rl[1];
                bl[p * 2 + 1][0] = rl[2]; bl[p * 2 + 1][1] = rl[3];
            }
            // A fragments streamed per mf (8 regs live)
            #pragma unroll
            for (int mf = 0; mf < 4; ++mf) {
                uint32_t ah[4], al[4];
                const uint32_t ra = stg + (uint32_t)(wm + mf * 16) * ROWB + laneA + kb;
                ldm_x4(ah, ra + 0 * TILEB);
                ldm_x4(al, ra + 1 * TILEB);
                #pragma unroll
                for (int nf = 0; nf < 4; ++nf) {
                    mma16816(acc[mf][nf], ah, bh[nf]);
                    mma16816(acc[mf][nf], ah, bl[nf]);
                    mma16816(acc[mf][nf], al, bh[nf]);
                }
            }
        }
        __syncthreads();   // all reads of stage s done before next iter overwrites
    }

    const int rbase = lane >> 2;
    const int cbase = (lane & 3) * 2;
    #pragma unroll
    for (int mf = 0; mf < 4; ++mf) {
        #pragma unroll
        for (int nf = 0; nf < 4; ++nf) {
            const int col = n0 + wn + nf * 8 + cbase;
            const float2 bb = *(const float2*)&bias[col];
            #pragma unroll
            for (int h = 0; h < 2; ++h) {
                const int row = m0 + wm + mf * 16 + rbase + h * 8;
                float2 rv;
                rv.x = acc[mf][nf][h * 2 + 0] + bb.x;
                rv.y = acc[mf][nf][h * 2 + 1] + bb.y;
                if (EPI == 1) { rv.x = gelu_f(rv.x); rv.y = gelu_f(rv.y); }
                if (EPI == 2) {
                    const float2 rr = *(const float2*)&R[(size_t)row * N + col];
                    rv.x += rr.x; rv.y += rr.y;
                }
                if (Cf) *(float2*)&Cf[(size_t)row * N + col] = rv;
                if (Ch) {
                    uint32_t hi, lo;
                    bfsplit2(rv.x, rv.y, hi, lo);
                    *(uint32_t*)&Ch[(size_t)row * N + col] = hi;
                    *(uint32_t*)&Cl[(size_t)row * N + col] = lo;
                }
            }
        }
    }
    #undef LOAD_STAGE
}

// ---------------------------------------------------------------------------
// fp32 -> bf16 hi/lo split kernels
// ---------------------------------------------------------------------------
__device__ __forceinline__ void split1(float v, unsigned short& h, unsigned short& l) {
    __nv_bfloat16 hb = __float2bfloat16(v);
    __nv_bfloat16 lb = __float2bfloat16(v - __bfloat162float(hb));
    h = *(unsigned short*)&hb;
    l = *(unsigned short*)&lb;
}

__global__ __launch_bounds__(256)
void split_kernel(const float* __restrict__ X, unsigned short* __restrict__ hi,
                  unsigned short* __restrict__ lo, int n4)
{
    int i = blockIdx.x * 256 + threadIdx.x;
    if (i >= n4) return;
    float4 v = ((const float4*)X)[i];
    ushort4 h, l;
    split1(v.x, h.x, l.x); split1(v.y, h.y, l.y);
    split1(v.z, h.z, l.z); split1(v.w, h.w, l.w);
    ((ushort4*)hi)[i] = h;
    ((ushort4*)lo)[i] = l;
}

// transpose+split; z-fused for up to 4 equal-shaped weights
__global__ __launch_bounds__(256)
void tsplit_kernel(const float* __restrict__ W0, const float* __restrict__ W1,
                   const float* __restrict__ W2, const float* __restrict__ W3,
                   unsigned short* __restrict__ Thi, unsigned short* __restrict__ Tlo,
                   size_t zstride, int K, int N)
{
    __shared__ float s[32][33];
    const int z = blockIdx.z;
    const float* W = (z == 0) ? W0 : (z == 1) ? W1 : (z == 2) ? W2 : W3;
    unsigned short* Th = Thi + zstride * z;
    unsigned short* Tl = Tlo + zstride * z;
    const int tx = threadIdx.x, ty = threadIdx.y;
    const int nb = blockIdx.x * 32, kb = blockIdx.y * 32;
    #pragma unroll
    for (int i = 0; i < 4; ++i)
        s[ty + i * 8][tx] = W[(size_t)(kb + ty + i * 8) * N + nb + tx];
    __syncthreads();
    #pragma unroll
    for (int i = 0; i < 4; ++i) {
        const float v = s[tx][ty + i * 8];
        unsigned short h, l;
        split1(v, h, l);
        const size_t o = (size_t)(nb + ty + i * 8) * K + kb + tx;
        Th[o] = h; Tl[o] = l;
    }
}

// ---------------------------------------------------------------------------
// Flash attention via mma.sync; V in NATURAL layout via ldmatrix.trans.
// 2-stage KV pipeline (R8 best config — unchanged).
// ---------------------------------------------------------------------------
#define AROWB   144
#define ATT_QLO 18432
#define ATT_KV  36864
#define ATT_STG 36864
#define ATT_MB  (ATT_KV + 2 * ATT_STG)
#define ATT_SMEM (ATT_MB + 512)

__global__ __launch_bounds__(256, 1)
void attn_mma_kernel(const unsigned short* __restrict__ Qhi,
                     const unsigned short* __restrict__ Qlo,
                     const unsigned short* __restrict__ Khi,
                     const unsigned short* __restrict__ Klo,
                     const unsigned short* __restrict__ Vhi,
                     const unsigned short* __restrict__ Vlo,
                     const int* __restrict__ mask,
                     unsigned short* __restrict__ Yhi,
                     unsigned short* __restrict__ Ylo)
{
    extern __shared__ __align__(128) char smem[];
    const uint32_t sb = smem_u32(smem);
    const int t    = threadIdx.x;
    const int lane = t & 31;
    const int w    = t >> 5;
    const int q0   = blockIdx.x * 128;
    const int bh   = blockIdx.y;
    const int tokb = (bh >> 4) * 2048;
    const int colb = (bh & 15) * 64;

    const uint32_t laneA = (uint32_t)(lane & 15) * AROWB + (lane >> 4) * 16;
    const uint32_t laneB = (uint32_t)((lane & 7) + ((lane >> 4) << 3)) * AROWB
                         + ((lane >> 3) & 1) * 16;
    const uint32_t laneBT = (uint32_t)((lane & 7) + ((lane >> 3) & 1) * 8) * AROWB
                          + (lane >> 4) * 16;

    {
        const int row = t >> 1;
        const size_t g = (size_t)(tokb + q0 + row) * 1024 + colb;
        const uint32_t sr = (uint32_t)row * AROWB;
        #pragma unroll
        for (int i = 0; i < 4; ++i) {
            const int ch = (t & 1) * 4 + i;
            cpa16(sb + sr + ch * 16,           Qhi + g + ch * 8);
            cpa16(sb + ATT_QLO + sr + ch * 16, Qlo + g + ch * 8);
        }
    }

    auto LOADKV = [&](int tile, int s) {
        const int kv0 = tile * 64;
        const int row = t >> 2;
        const int q2  = t & 3;
        const uint32_t st = sb + ATT_KV + s * ATT_STG;
        const size_t gk = (size_t)(tokb + kv0 + row) * 1024 + colb;
        const uint32_t sr = (uint32_t)row * AROWB;
        #pragma unroll
        for (int i = 0; i < 2; ++i) {
            const int ch = q2 * 2 + i;
            cpa16(st +         sr + ch * 16, Khi + gk + ch * 8);
            cpa16(st +  9216 + sr + ch * 16, Klo + gk + ch * 8);
            cpa16(st + 18432 + sr + ch * 16, Vhi + gk + ch * 8);
            cpa16(st + 27648 + sr + ch * 16, Vlo + gk + ch * 8);
        }
        if (t < 64) {
            float* mb = (float*)(smem + ATT_MB) + s * 64;
            mb[t] = (mask[tokb + kv0 + t] == 0) ? -1e30f : 0.0f;
        }
    };

    LOADKV(0, 0); cp_commit();
    LOADKV(1, 1); cp_commit();

    cp_wait<1>();
    __syncthreads();

    uint32_t qh[4][4], ql[4][4];
    #pragma unroll
    for (int fk = 0; fk < 4; ++fk) {
        const uint32_t ra = sb + (uint32_t)(w * 16) * AROWB + laneA + fk * 32;
        ldm_x4(qh[fk], ra);
        ldm_x4(ql[fk], ra + ATT_QLO);
    }

    float of[8][4];
    #pragma unroll
    for (int i = 0; i < 8; ++i)
        #pragma unroll
        for (int j = 0; j < 4; ++j) of[i][j] = 0.0f;
    float mA = -1e30f, mB = -1e30f, lA = 0.0f, lB = 0.0f;
    const int c0 = (lane & 3) * 2;

    for (int tile = 0; tile < 32; ++tile) {
        const int s = tile & 1;
        if (tile > 0) { cp_wait<1>(); __syncthreads(); }
        const uint32_t kst = sb + ATT_KV + s * ATT_STG;
        const float* mb = (const float*)(smem + ATT_MB) + s * 64;

        float sf[8][4];
        #pragma unroll
        for (int i = 0; i < 8; ++i)
            #pragma unroll
            for (int j = 0; j < 4; ++j) sf[i][j] = 0.0f;

        #pragma unroll
        for (int fk = 0; fk < 4; ++fk) {
            uint32_t kh[8][2], kl[8][2];
            #pragma unroll
            for (int p = 0; p < 4; ++p) {
                uint32_t r0[4], r1[4];
                const uint32_t ra = kst + (uint32_t)(p * 16) * AROWB + laneB + fk * 32;
                ldm_x4(r0, ra);
                ldm_x4(r1, ra + 9216);
                kh[p * 2 + 0][0] = r0[0]; kh[p * 2 + 0][1] = r0[1];
                kh[p * 2 + 1][0] = r0[2]; kh[p * 2 + 1][1] = r0[3];
                kl[p * 2 + 0][0] = r1[0]; kl[p * 2 + 0][1] = r1[1];
                kl[p * 2 + 1][0] = r1[2]; kl[p * 2 + 1][1] = r1[3];
            }
            #pragma unroll
            for (int nf = 0; nf < 8; ++nf) {
                mma16816(sf[nf], qh[fk], kh[nf]);
                mma16816(sf[nf], qh[fk], kl[nf]);
                mma16816(sf[nf], ql[fk], kh[nf]);
            }
        }

        float pmA = -1e30f, pmB = -1e30f;
        #pragma unroll
        for (int nf = 0; nf < 8; ++nf) {
            const float m0 = mb[nf * 8 + c0];
            const float m1 = mb[nf * 8 + c0 + 1];
            sf[nf][0] = fmaf(sf[nf][0], 0.125f, m0);
            sf[nf][1] = fmaf(sf[nf][1], 0.125f, m1);
            sf[nf][2] = fmaf(sf[nf][2], 0.125f, m0);
            sf[nf][3] = fmaf(sf[nf][3], 0.125f, m1);
            pmA = fmaxf(pmA, fmaxf(sf[nf][0], sf[nf][1]));
            pmB = fmaxf(pmB, fmaxf(sf[nf][2], sf[nf][3]));
        }
        pmA = fmaxf(pmA, __shfl_xor_sync(0xffffffffu, pmA, 1));
        pmA = fmaxf(pmA, __shfl_xor_sync(0xffffffffu, pmA, 2));
        pmB = fmaxf(pmB, __shfl_xor_sync(0xffffffffu, pmB, 1));
        pmB = fmaxf(pmB, __shfl_xor_sync(0xffffffffu, pmB, 2));
        const float mnA = fmaxf(mA, pmA), mnB = fmaxf(mB, pmB);
        const float alA = __expf(mA - mnA), alB = __expf(mB - mnB);
        mA = mnA; mB = mnB;
        float rsA = 0.0f, rsB = 0.0f;
        #pragma unroll
        for (int nf = 0; nf < 8; ++nf) {
            sf[nf][0] = __expf(sf[nf][0] - mnA);
            sf[nf][1] = __expf(sf[nf][1] - mnA);
            sf[nf][2] = __expf(sf[nf][2] - mnB);
            sf[nf][3] = __expf(sf[nf][3] - mnB);
            rsA += sf[nf][0] + sf[nf][1];
            rsB += sf[nf][2] + sf[nf][3];
        }
        rsA += __shfl_xor_sync(0xffffffffu, rsA, 1);
        rsA += __shfl_xor_sync(0xffffffffu, rsA, 2);
        rsB += __shfl_xor_sync(0xffffffffu, rsB, 1);
        rsB += __shfl_xor_sync(0xffffffffu, rsB, 2);
        lA = lA * alA + rsA;
        lB = lB * alB + rsB;
        #pragma unroll
        for (int nf = 0; nf < 8; ++nf) {
            of[nf][0] *= alA; of[nf][1] *= alA;
            of[nf][2] *= alB; of[nf][3] *= alB;
        }

        #pragma unroll
        for (int fk = 0; fk < 4; ++fk) {
            uint32_t aHi[4], aLo[4];
            bfsplit2(sf[2 * fk][0],     sf[2 * fk][1],     aHi[0], aLo[0]);
            bfsplit2(sf[2 * fk][2],     sf[2 * fk][3],     aHi[1], aLo[1]);
            bfsplit2(sf[2 * fk + 1][0], sf[2 * fk + 1][1], aHi[2], aLo[2]);
            bfsplit2(sf[2 * fk + 1][2], sf[2 * fk + 1][3], aHi[3], aLo[3]);
            uint32_t vh[8][2], vl[8][2];
            #pragma unroll
            for (int p = 0; p < 4; ++p) {
                uint32_t r0[4], r1[4];
                const uint32_t ra = kst + 18432 + (uint32_t)(fk * 16) * AROWB
                                  + laneBT + p * 32;
                ldm_x4_t(r0, ra);
                ldm_x4_t(r1, ra + 9216);
                vh[p * 2 + 0][0] = r0[0]; vh[p * 2 + 0][1] = r0[1];
                vh[p * 2 + 1][0] = r0[2]; vh[p * 2 + 1][1] = r0[3];
                vl[p * 2 + 0][0] = r1[0]; vl[p * 2 + 0][1] = r1[1];
                vl[p * 2 + 1][0] = r1[2]; vl[p * 2 + 1][1] = r1[3];
            }
            #pragma unroll
            for (int nf = 0; nf < 8; ++nf) {
                mma16816(of[nf], aHi, vh[nf]);
                mma16816(of[nf], aHi, vl[nf]);
                mma16816(of[nf], aLo, vh[nf]);
            }
        }

        __syncthreads();
        if (tile + 2 < 32) LOADKV(tile + 2, s);
        cp_commit();
    }

    const float iA = 1.0f / lA, iB = 1.0f / lB;
    const int rA = lane >> 2;
    const int rowA = tokb + q0 + w * 16 + rA;
    #pragma unroll
    for (int nf = 0; nf < 8; ++nf) {
        const int col = colb + nf * 8 + c0;
        uint32_t h0, l0, h1, l1;
        bfsplit2(of[nf][0] * iA, of[nf][1] * iA, h0, l0);
        bfsplit2(of[nf][2] * iB, of[nf][3] * iB, h1, l1);
        *(uint32_t*)&Yhi[(size_t)rowA * 1024 + col]       = h0;
        *(uint32_t*)&Ylo[(size_t)rowA * 1024 + col]       = l0;
        *(uint32_t*)&Yhi[(size_t)(rowA + 8) * 1024 + col] = h1;
        *(uint32_t*)&Ylo[(size_t)(rowA + 8) * 1024 + col] = l1;
    }
}

// ---------------------------------------------------------------------------
// LayerNorm: one row per CTA; optional fused bf16 hi/lo split output
// ---------------------------------------------------------------------------
__global__ __launch_bounds__(256)
void ln_kernel(const float* __restrict__ X, const float* __restrict__ w,
               const float* __restrict__ b, float* __restrict__ out,
               unsigned short* __restrict__ hi, unsigned short* __restrict__ lo)
{
    __shared__ float red[2][8];
    const int t = threadIdx.x;
    const size_t row = blockIdx.x;
    float4 xv = *(const float4*)&X[row * 1024 + t * 4];
    float s  = xv.x + xv.y + xv.z + xv.w;
    float s2 = xv.x * xv.x + xv.y * xv.y + xv.z * xv.z + xv.w * xv.w;
    #pragma unroll
    for (int off = 16; off; off >>= 1) {
        s  += __shfl_xor_sync(0xffffffffu, s,  off);
        s2 += __shfl_xor_sync(0xffffffffu, s2, off);
    }
    if ((t & 31) == 0) { red[0][t >> 5] = s; red[1][t >> 5] = s2; }
    __syncthreads();
    float S = 0.0f, S2 = 0.0f;
    #pragma unroll
    for (int i = 0; i < 8; ++i) { S += red[0][i]; S2 += red[1][i]; }
    const float mean = S * (1.0f / 1024.0f);
    const float var  = S2 * (1.0f / 1024.0f) - mean * mean;
    const float rstd = rsqrtf(var + 1e-5f);
    float4 wv = *(const float4*)&w[t * 4];
    float4 bv = *(const float4*)&b[t * 4];
    float4 r;
    r.x = (xv.x - mean) * rstd * wv.x + bv.x;
    r.y = (xv.y - mean) * rstd * wv.y + bv.y;
    r.z = (xv.z - mean) * rstd * wv.z + bv.z;
    r.w = (xv.w - mean) * rstd * wv.w + bv.w;
    if (out) *(float4*)&out[row * 1024 + t * 4] = r;
    if (hi) {
        uint32_t h0, l0, h1, l1;
        bfsplit2(r.x, r.y, h0, l0);
        bfsplit2(r.z, r.w, h1, l1);
        uint2 hv = make_uint2(h0, h1), lv = make_uint2(l0, l1);
        *(uint2*)&hi[row * 1024 + t * 4] = hv;
        *(uint2*)&lo[row * 1024 + t * 4] = lv;
    }
}

// ---------------------------------------------------------------------------
// launch
// ---------------------------------------------------------------------------
extern "C" void kernel_launch(void* const* d_in, const int* in_sizes, int n_in,
                              void* d_out, int out_size)
{
    (void)in_sizes; (void)n_in; (void)out_size;
    const float* x    = (const float*)d_in[0];
    const int*   mask = (const int*)  d_in[1];
    const float* WQ   = (const float*)d_in[2];
    const float* bQ   = (const float*)d_in[3];
    const float* WK   = (const float*)d_in[4];
    const float* bK   = (const float*)d_in[5];
    const float* WV   = (const float*)d_in[6];
    const float* bV   = (const float*)d_in[7];
    const float* WY   = (const float*)d_in[8];
    const float* bY   = (const float*)d_in[9];
    const float* ln1w = (const float*)d_in[10];
    const float* ln1b = (const float*)d_in[11];
    const float* ln2w = (const float*)d_in[12];
    const float* ln2b = (const float*)d_in[13];
    const float* W1   = (const float*)d_in[14];
    const float* b1   = (const float*)d_in[15];
    const float* W2   = (const float*)d_in[16];
    const float* b2   = (const float*)d_in[17];
    float* out = (float*)d_out;

    float *Qp, *Kp, *Vp, *Yp;
    unsigned short *Ahi, *Alo, *Whi, *Wlo;
    unsigned short *Qhi, *Qlo, *Khi, *Klo, *Vhi, *Vlo;
    cudaGetSymbolAddress((void**)&Qp,  g_Q);
    cudaGetSymbolAddress((void**)&Kp,  g_K);
    cudaGetSymbolAddress((void**)&Vp,  g_V);
    cudaGetSymbolAddress((void**)&Yp,  g_Y);
    cudaGetSymbolAddress((void**)&Ahi, g_Ahi);
    cudaGetSymbolAddress((void**)&Alo, g_Alo);
    cudaGetSymbolAddress((void**)&Whi, g_Whi);
    cudaGetSymbolAddress((void**)&Wlo, g_Wlo);
    cudaGetSymbolAddress((void**)&Qhi, g_Qhi);
    cudaGetSymbolAddress((void**)&Qlo, g_Qlo);
    cudaGetSymbolAddress((void**)&Khi, g_Khi);
    cudaGetSymbolAddress((void**)&Klo, g_Klo);
    cudaGetSymbolAddress((void**)&Vhi, g_Vhi);
    cudaGetSymbolAddress((void**)&Vlo, g_Vlo);

    unsigned short* Yhi = (unsigned short*)Yp;
    unsigned short* Ylo = (unsigned short*)Yp + (size_t)4096 * 1024;

    const size_t MB = (size_t)1024 * 1024;

    cudaFuncSetAttribute(tgemm_kernel<0>,
                         cudaFuncAttributeMaxDynamicSharedMemorySize, TG_SMEM);
    cudaFuncSetAttribute(tgemm_kernel<1>,
                         cudaFuncAttributeMaxDynamicSharedMemorySize, TG_SMEM);
    cudaFuncSetAttribute(tgemm_kernel<2>,
                         cudaFuncAttributeMaxDynamicSharedMemorySize, TG_SMEM);
    cudaFuncSetAttribute(attn_mma_kernel,
                         cudaFuncAttributeMaxDynamicSharedMemorySize, ATT_SMEM);

    dim3 blk(256);
    dim3 tsb(32, 8);

    // weight transposes
    tsplit_kernel<<<dim3(32, 32, 4), tsb>>>(WQ, WK, WV, WY, Whi, Wlo, MB, 1024, 1024);
    tsplit_kernel<<<dim3(128, 32, 1), tsb>>>(W1, W1, W1, W1, Whi + 4 * MB, Wlo + 4 * MB,
                                             0, 1024, 4096);
    tsplit_kernel<<<dim3(32, 128, 1), tsb>>>(W2, W2, W2, W2, Whi + 8 * MB, Wlo + 8 * MB,
                                             0, 4096, 1024);

    // x split
    split_kernel<<<4096, blk>>>(x, Ahi, Alo, (4096 * 1024) / 4);

    // QKV: all three outputs as bf16 splits (V natural layout)
    tgemm_kernel<0><<<dim3(8, 32, 3), blk, TG_SMEM>>>(
        Ahi, Alo, Whi, Wlo, MB, bQ, bK, bV, nullptr,
        nullptr, nullptr, nullptr,
        Qhi, Khi, Vhi,
        Qlo, Klo, Vlo,
        4096, 1024, 1024);

    // attention -> Yhi/Ylo bf16
    attn_mma_kernel<<<dim3(16, 32), blk, ATT_SMEM>>>(
        Qhi, Qlo, Khi, Klo, Vhi, Vlo, mask, Yhi, Ylo);

    // out-proj + residual x -> fp32 g_Q
    tgemm_kernel<2><<<dim3(8, 32, 1), blk, TG_SMEM>>>(
        Yhi, Ylo, Whi + 3 * MB, Wlo + 3 * MB, 0, bY, bY, bY, x,
        Qp, nullptr, nullptr,
        nullptr, nullptr, nullptr,
        nullptr, nullptr, nullptr,
        4096, 1024, 1024);

    // h = LN1 -> fp32 g_K + bf16 split (Qhi/Qlo reused)
    ln_kernel<<<4096, blk>>>(Qp, ln1w, ln1b, Kp, Qhi, Qlo);

    // FFN1: gelu(h@W1+b1) -> bf16 split only
    tgemm_kernel<1><<<dim3(32, 32, 1), blk, TG_SMEM>>>(
        Qhi, Qlo, Whi + 4 * MB, Wlo + 4 * MB, 0, b1, b1, b1, nullptr,
        nullptr, nullptr, nullptr,
        Ahi, nullptr, nullptr,
        Alo, nullptr, nullptr,
        4096, 4096, 1024);

    // FFN2: ff@W2+b2+h -> fp32 g_V
    tgemm_kernel<2><<<dim3(8, 32, 1), blk, TG_SMEM>>>(
        Ahi, Alo, Whi + 8 * MB, Wlo + 8 * MB, 0, b2, b2, b2, Kp,
        Vp, nullptr, nullptr,
        nullptr, nullptr, nullptr,
        nullptr, nullptr, nullptr,
        4096, 1024, 4096);

    // out = LN2
    ln_kernel<<<4096, blk>>>(Vp, ln2w, ln2b, out, nullptr, nullptr);
}